// round 2
// baseline (speedup 1.0000x reference)
#include <cuda_runtime.h>
#include <cuda_bf16.h>
#include <math.h>

// ---------------------------------------------------------------------------
// Problem dims (fixed)
// ---------------------------------------------------------------------------
#define BB 4
#define TQ 1024
#define TK 1024
#define DD 1024
#define HH 16
#define DK 64
#define DV 64
#define MROWS (BB * TQ)          // 4096
#define BH (BB * HH)             // 64

// ---------------------------------------------------------------------------
// Scratch (device globals — no allocations allowed)
// ---------------------------------------------------------------------------
__device__ float g_x1[MROWS * DD];
__device__ float g_y1[BB * TK * DD];
__device__ float g_q [MROWS * DD];
__device__ float g_k [BB * TK * DD];
__device__ float g_v [BB * TK * DD];
__device__ float g_logits[(size_t)BH * TQ * TK];   // 256 MB
__device__ float g_attn[MROWS * DD];
__device__ float g_x2 [MROWS * DD];
__device__ float g_t1 [MROWS * DD];
__device__ float g_h  [MROWS * DD];
__device__ float g_t2 [MROWS * DD];

// ---------------------------------------------------------------------------
// LayerNorm (affine, eps=1e-5) + ReLU, one block per row of 1024
// ---------------------------------------------------------------------------
__global__ void ln_relu_kernel(const float* __restrict__ in,
                               const float* __restrict__ gamma,
                               const float* __restrict__ beta,
                               float* __restrict__ out) {
    int row = blockIdx.x;
    int tid = threadIdx.x;            // 256 threads, 4 floats each
    const float* p = in + (size_t)row * DD + tid * 4;
    float4 xv = *(const float4*)p;

    float s  = xv.x + xv.y + xv.z + xv.w;
    float ss = xv.x*xv.x + xv.y*xv.y + xv.z*xv.z + xv.w*xv.w;

    // warp reduce
    #pragma unroll
    for (int off = 16; off > 0; off >>= 1) {
        s  += __shfl_xor_sync(0xffffffffu, s,  off);
        ss += __shfl_xor_sync(0xffffffffu, ss, off);
    }
    __shared__ float sbuf[8], ssbuf[8];
    __shared__ float smean, sinv;
    int lane = tid & 31, warp = tid >> 5;
    if (lane == 0) { sbuf[warp] = s; ssbuf[warp] = ss; }
    __syncthreads();
    if (tid == 0) {
        float ts = 0.f, tss = 0.f;
        #pragma unroll
        for (int i = 0; i < 8; i++) { ts += sbuf[i]; tss += ssbuf[i]; }
        float mean = ts * (1.0f / DD);
        float var  = tss * (1.0f / DD) - mean * mean;
        smean = mean;
        sinv  = rsqrtf(var + 1e-5f);
    }
    __syncthreads();
    float m = smean, inv = sinv;

    int c = tid * 4;
    float4 g4 = *(const float4*)(gamma + c);
    float4 b4 = *(const float4*)(beta  + c);
    float4 o;
    o.x = fmaxf(0.f, (xv.x - m) * inv * g4.x + b4.x);
    o.y = fmaxf(0.f, (xv.y - m) * inv * g4.y + b4.y);
    o.z = fmaxf(0.f, (xv.z - m) * inv * g4.z + b4.z);
    o.w = fmaxf(0.f, (xv.w - m) * inv * g4.w + b4.w);
    *(float4*)(out + (size_t)row * DD + c) = o;
}

// ---------------------------------------------------------------------------
// SGEMM: C[M,N] = A[M,K] @ B[K,N] + bias[N] (+ res[M,N]); row-major.
// 128x128 tile, BK=8, 256 threads, 8x8 micro-tile. Dims multiples of 128/8.
// ---------------------------------------------------------------------------
__global__ void __launch_bounds__(256, 2)
sgemm_bias_kernel(const float* __restrict__ A, const float* __restrict__ B,
                  const float* __restrict__ bias, const float* __restrict__ res,
                  float* __restrict__ C, int M, int N, int K) {
    __shared__ float As[8][128];
    __shared__ float Bs[8][128];

    int tid = threadIdx.x;
    int bm = blockIdx.y * 128;
    int bn = blockIdx.x * 128;

    int arow = tid >> 1, acol = (tid & 1) * 4;       // A tile: 128 rows x 8 cols
    int brow = tid >> 5, bcol = (tid & 31) * 4;      // B tile: 8 rows x 128 cols
    int tx = (tid & 15) * 8, ty = (tid >> 4) * 8;

    const float* Aptr = A + (size_t)(bm + arow) * K + acol;
    const float* Bptr = B + (size_t)brow * N + bn + bcol;

    float acc[8][8];
    #pragma unroll
    for (int i = 0; i < 8; i++)
        #pragma unroll
        for (int j = 0; j < 8; j++) acc[i][j] = 0.f;

    for (int k0 = 0; k0 < K; k0 += 8) {
        float4 a = *(const float4*)(Aptr + k0);
        float4 b = *(const float4*)(Bptr + (size_t)k0 * N);
        As[acol + 0][arow] = a.x;
        As[acol + 1][arow] = a.y;
        As[acol + 2][arow] = a.z;
        As[acol + 3][arow] = a.w;
        *(float4*)&Bs[brow][bcol] = b;
        __syncthreads();

        #pragma unroll
        for (int k = 0; k < 8; k++) {
            float ar[8], br[8];
            #pragma unroll
            for (int i = 0; i < 8; i++) ar[i] = As[k][ty + i];
            #pragma unroll
            for (int j = 0; j < 8; j++) br[j] = Bs[k][tx + j];
            #pragma unroll
            for (int i = 0; i < 8; i++)
                #pragma unroll
                for (int j = 0; j < 8; j++)
                    acc[i][j] = fmaf(ar[i], br[j], acc[i][j]);
        }
        __syncthreads();
    }

    float bb[8];
    #pragma unroll
    for (int j = 0; j < 8; j++) bb[j] = bias[bn + tx + j];

    #pragma unroll
    for (int i = 0; i < 8; i++) {
        size_t rowoff = (size_t)(bm + ty + i) * N + bn + tx;
        #pragma unroll
        for (int j = 0; j < 8; j++) {
            float c = acc[i][j] + bb[j];
            if (res) c += res[rowoff + j];
            C[rowoff + j] = c;
        }
    }
}

// ---------------------------------------------------------------------------
// Scores: S[bh, t, T] = 0.125 * sum_d Q[b,t,h,d] * K[b,T,h,d]
// grid: (TK/64, TQ/64, BH), 256 threads, 64x64 tile, full K=64 in smem.
// ---------------------------------------------------------------------------
__global__ void __launch_bounds__(256, 2)
scores_kernel(const float* __restrict__ Q, const float* __restrict__ Kmat,
              float* __restrict__ S) {
    __shared__ float Qs[64][68];
    __shared__ float Ks[64][68];

    int tid = threadIdx.x;
    int bh = blockIdx.z;
    int b = bh >> 4, h = bh & 15;
    int t0 = blockIdx.y * 64;
    int T0 = blockIdx.x * 64;

    const float* qb = Q    + (size_t)b * TQ * DD + h * DK;
    const float* kb = Kmat + (size_t)b * TK * DD + h * DK;

    #pragma unroll
    for (int it = 0; it < 4; it++) {
        int idx = tid + it * 256;          // 0..1023 float4s
        int r = idx >> 4;
        int c = (idx & 15) * 4;
        float4 qa = *(const float4*)(qb + (size_t)(t0 + r) * DD + c);
        float4 ka = *(const float4*)(kb + (size_t)(T0 + r) * DD + c);
        Qs[r][c] = qa.x; Qs[r][c+1] = qa.y; Qs[r][c+2] = qa.z; Qs[r][c+3] = qa.w;
        Ks[r][c] = ka.x; Ks[r][c+1] = ka.y; Ks[r][c+2] = ka.z; Ks[r][c+3] = ka.w;
    }
    __syncthreads();

    int tx = (tid & 15) * 4, ty = (tid >> 4) * 4;
    float acc[4][4];
    #pragma unroll
    for (int i = 0; i < 4; i++)
        #pragma unroll
        for (int j = 0; j < 4; j++) acc[i][j] = 0.f;

    #pragma unroll 8
    for (int d = 0; d < 64; d++) {
        float a[4], bv[4];
        #pragma unroll
        for (int i = 0; i < 4; i++) a[i]  = Qs[ty + i][d];
        #pragma unroll
        for (int j = 0; j < 4; j++) bv[j] = Ks[tx + j][d];
        #pragma unroll
        for (int i = 0; i < 4; i++)
            #pragma unroll
            for (int j = 0; j < 4; j++)
                acc[i][j] = fmaf(a[i], bv[j], acc[i][j]);
    }

    float* out = S + ((size_t)bh * TQ) * TK;
    #pragma unroll
    for (int i = 0; i < 4; i++) {
        size_t off = (size_t)(t0 + ty + i) * TK + T0 + tx;
        #pragma unroll
        for (int j = 0; j < 4; j++)
            out[off + j] = acc[i][j] * 0.125f;
    }
}

// ---------------------------------------------------------------------------
// Masked softmax over rows of 1024 (in-place on logits).
// mask is [B, TK] of int32 (0/1); 0 -> -1e30.
// ---------------------------------------------------------------------------
__global__ void softmax_mask_kernel(float* __restrict__ S,
                                    const int* __restrict__ mask) {
    int row = blockIdx.x;                  // 0 .. BH*TQ-1
    int b = row >> 14;                     // / (HH*TQ)
    float* p = S + (size_t)row * TK;
    const int* mrow = mask + (size_t)b * TK;

    int c = threadIdx.x * 4;
    float4 v4 = *(const float4*)(p + c);
    int4  m4 = *(const int4*)(mrow + c);
    float v[4] = {v4.x, v4.y, v4.z, v4.w};
    if (!m4.x) v[0] = -1e30f;
    if (!m4.y) v[1] = -1e30f;
    if (!m4.z) v[2] = -1e30f;
    if (!m4.w) v[3] = -1e30f;

    float mx = fmaxf(fmaxf(v[0], v[1]), fmaxf(v[2], v[3]));
    #pragma unroll
    for (int off = 16; off > 0; off >>= 1)
        mx = fmaxf(mx, __shfl_xor_sync(0xffffffffu, mx, off));
    __shared__ float mbuf[8], sbuf[8];
    __shared__ float smax, ssum;
    int lane = threadIdx.x & 31, warp = threadIdx.x >> 5;
    if (lane == 0) mbuf[warp] = mx;
    __syncthreads();
    if (threadIdx.x == 0) {
        float m = mbuf[0];
        #pragma unroll
        for (int i = 1; i < 8; i++) m = fmaxf(m, mbuf[i]);
        smax = m;
    }
    __syncthreads();
    float m = smax;

    float e[4], s = 0.f;
    #pragma unroll
    for (int t = 0; t < 4; t++) { e[t] = __expf(v[t] - m); s += e[t]; }
    #pragma unroll
    for (int off = 16; off > 0; off >>= 1)
        s += __shfl_xor_sync(0xffffffffu, s, off);
    if (lane == 0) sbuf[warp] = s;
    __syncthreads();
    if (threadIdx.x == 0) {
        float ts = 0.f;
        #pragma unroll
        for (int i = 0; i < 8; i++) ts += sbuf[i];
        ssum = ts;
    }
    __syncthreads();
    float rinv = 1.0f / ssum;

    float4 o = {e[0] * rinv, e[1] * rinv, e[2] * rinv, e[3] * rinv};
    *(float4*)(p + c) = o;
}

// ---------------------------------------------------------------------------
// attn[b,t,h,:] = sum_T W[bh,t,T] * V[b,T,h,:]
// grid: (1, TQ/64, BH); tile 64 t-rows x 64 d-cols, loop T in 32-chunks.
// ---------------------------------------------------------------------------
__global__ void __launch_bounds__(256, 2)
attnv_kernel(const float* __restrict__ W, const float* __restrict__ V,
             float* __restrict__ out) {
    __shared__ float Ws[64][33];
    __shared__ float Vs[32][68];

    int tid = threadIdx.x;
    int bh = blockIdx.z;
    int b = bh >> 4, h = bh & 15;
    int t0 = blockIdx.y * 64;

    const float* Wbase = W + ((size_t)bh * TQ) * TK;
    const float* Vbase = V + (size_t)b * TK * DD + h * DV;

    int tx = (tid & 15) * 4, ty = (tid >> 4) * 4;
    float acc[4][4];
    #pragma unroll
    for (int i = 0; i < 4; i++)
        #pragma unroll
        for (int j = 0; j < 4; j++) acc[i][j] = 0.f;

    for (int T0 = 0; T0 < TK; T0 += 32) {
        #pragma unroll
        for (int it = 0; it < 2; it++) {
            int idx = tid + it * 256;      // 0..511
            int wr = idx >> 3, wc = (idx & 7) * 4;     // Ws: 64 x 32
            float4 w4 = *(const float4*)(Wbase + (size_t)(t0 + wr) * TK + T0 + wc);
            Ws[wr][wc] = w4.x; Ws[wr][wc+1] = w4.y; Ws[wr][wc+2] = w4.z; Ws[wr][wc+3] = w4.w;
            int vr = idx >> 4, vc = (idx & 15) * 4;    // Vs: 32 x 64
            float4 v4 = *(const float4*)(Vbase + (size_t)(T0 + vr) * DD + vc);
            Vs[vr][vc] = v4.x; Vs[vr][vc+1] = v4.y; Vs[vr][vc+2] = v4.z; Vs[vr][vc+3] = v4.w;
        }
        __syncthreads();

        #pragma unroll 8
        for (int kk = 0; kk < 32; kk++) {
            float a[4], bv[4];
            #pragma unroll
            for (int i = 0; i < 4; i++) a[i]  = Ws[ty + i][kk];
            #pragma unroll
            for (int j = 0; j < 4; j++) bv[j] = Vs[kk][tx + j];
            #pragma unroll
            for (int i = 0; i < 4; i++)
                #pragma unroll
                for (int j = 0; j < 4; j++)
                    acc[i][j] = fmaf(a[i], bv[j], acc[i][j]);
        }
        __syncthreads();
    }

    #pragma unroll
    for (int i = 0; i < 4; i++) {
        size_t off = (size_t)(b * TQ + t0 + ty + i) * DD + h * DV + tx;
        #pragma unroll
        for (int j = 0; j < 4; j++)
            out[off + j] = acc[i][j];
    }
}

// ---------------------------------------------------------------------------
// Launch
// ---------------------------------------------------------------------------
extern "C" void kernel_launch(void* const* d_in, const int* in_sizes, int n_in,
                              void* d_out, int out_size) {
    const float* x      = (const float*)d_in[0];
    const float* y      = (const float*)d_in[1];
    const int*   mask   = (const int*)d_in[2];
    const float* ln1_g  = (const float*)d_in[3];
    const float* ln1_b  = (const float*)d_in[4];
    const float* ln2_g  = (const float*)d_in[5];
    const float* ln2_b  = (const float*)d_in[6];
    const float* q_w    = (const float*)d_in[7];
    const float* q_b    = (const float*)d_in[8];
    const float* k_w    = (const float*)d_in[9];
    const float* k_b    = (const float*)d_in[10];
    const float* v_w    = (const float*)d_in[11];
    const float* v_b    = (const float*)d_in[12];
    const float* o_w    = (const float*)d_in[13];
    const float* o_b    = (const float*)d_in[14];
    const float* mln1_g = (const float*)d_in[15];
    const float* mln1_b = (const float*)d_in[16];
    const float* l1_w   = (const float*)d_in[17];
    const float* l1_b   = (const float*)d_in[18];
    const float* mln2_g = (const float*)d_in[19];
    const float* mln2_b = (const float*)d_in[20];
    const float* l2_w   = (const float*)d_in[21];
    const float* l2_b   = (const float*)d_in[22];
    float* out = (float*)d_out;

    float *x1, *y1, *q, *k, *v, *logits, *attn, *x2, *t1, *hbuf, *t2;
    cudaGetSymbolAddress((void**)&x1,     g_x1);
    cudaGetSymbolAddress((void**)&y1,     g_y1);
    cudaGetSymbolAddress((void**)&q,      g_q);
    cudaGetSymbolAddress((void**)&k,      g_k);
    cudaGetSymbolAddress((void**)&v,      g_v);
    cudaGetSymbolAddress((void**)&logits, g_logits);
    cudaGetSymbolAddress((void**)&attn,   g_attn);
    cudaGetSymbolAddress((void**)&x2,     g_x2);
    cudaGetSymbolAddress((void**)&t1,     g_t1);
    cudaGetSymbolAddress((void**)&hbuf,   g_h);
    cudaGetSymbolAddress((void**)&t2,     g_t2);

    dim3 gemmGrid(DD / 128, MROWS / 128);   // (8, 32)

    // 1) pre-norms
    ln_relu_kernel<<<MROWS, 256>>>(x, ln1_g, ln1_b, x1);
    ln_relu_kernel<<<BB * TK, 256>>>(y, ln2_g, ln2_b, y1);

    // 2) projections
    sgemm_bias_kernel<<<gemmGrid, 256>>>(x1, q_w, q_b, nullptr, q, MROWS, DD, DD);
    sgemm_bias_kernel<<<gemmGrid, 256>>>(y1, k_w, k_b, nullptr, k, BB * TK, DD, DD);
    sgemm_bias_kernel<<<gemmGrid, 256>>>(y1, v_w, v_b, nullptr, v, BB * TK, DD, DD);

    // 3) attention
    scores_kernel<<<dim3(TK / 64, TQ / 64, BH), 256>>>(q, k, logits);
    softmax_mask_kernel<<<BH * TQ, 256>>>(logits, mask);
    attnv_kernel<<<dim3(1, TQ / 64, BH), 256>>>(logits, v, attn);

    // 4) output proj + residual
    sgemm_bias_kernel<<<gemmGrid, 256>>>(attn, o_w, o_b, x, x2, MROWS, DD, DD);

    // 5) MLP
    ln_relu_kernel<<<MROWS, 256>>>(x2, mln1_g, mln1_b, t1);
    sgemm_bias_kernel<<<gemmGrid, 256>>>(t1, l1_w, l1_b, nullptr, hbuf, MROWS, DD, DD);
    ln_relu_kernel<<<MROWS, 256>>>(hbuf, mln2_g, mln2_b, t2);
    sgemm_bias_kernel<<<gemmGrid, 256>>>(t2, l2_w, l2_b, nullptr, out, MROWS, DD, DD);
}

// round 4
// speedup vs baseline: 1.7016x; 1.7016x over previous
#include <cuda_runtime.h>
#include <cuda_bf16.h>
#include <math.h>
#include <stdint.h>

// ---------------------------------------------------------------------------
// Problem dims (fixed)
// ---------------------------------------------------------------------------
#define BB 4
#define TQ 1024
#define TK 1024
#define DD 1024
#define HH 16
#define DK 64
#define DV 64
#define MROWS (BB * TQ)          // 4096
#define BH (BB * HH)             // 64

// ---------------------------------------------------------------------------
// Scratch (device globals — no allocations allowed)
// ---------------------------------------------------------------------------
__device__ float g_x1[MROWS * DD];
__device__ float g_y1[BB * TK * DD];
__device__ float g_q [MROWS * DD];
__device__ float g_k [BB * TK * DD];
__device__ float g_v [BB * TK * DD];
__device__ float g_logits[(size_t)BH * TQ * TK];   // 256 MB
__device__ float g_attn[MROWS * DD];
__device__ float g_x2 [MROWS * DD];
__device__ float g_t1 [MROWS * DD];
__device__ float g_h  [MROWS * DD];
__device__ float g_t2 [MROWS * DD];
// bf16 split buffers
__device__ __nv_bfloat16 g_ahi[MROWS * DD];
__device__ __nv_bfloat16 g_alo[MROWS * DD];
__device__ __nv_bfloat16 g_bhi[DD * DD];
__device__ __nv_bfloat16 g_blo[DD * DD];

// ---------------------------------------------------------------------------
// PTX helpers (sm_80+ baseline features only — no tcgen05 on plain sm_103)
// ---------------------------------------------------------------------------
__device__ __forceinline__ uint32_t smem_u32(const void* p) {
    uint32_t a;
    asm("{ .reg .u64 t; cvta.to.shared.u64 t, %1; cvt.u32.u64 %0, t; }" : "=r"(a) : "l"(p));
    return a;
}
__device__ __forceinline__ void cpasync16(uint32_t dst, const void* src) {
    asm volatile("cp.async.cg.shared.global [%0], [%1], 16;" :: "r"(dst), "l"(src) : "memory");
}
#define CP_COMMIT() asm volatile("cp.async.commit_group;" ::: "memory")
#define CP_WAIT(n)  asm volatile("cp.async.wait_group %0;" :: "n"(n) : "memory")

__device__ __forceinline__ void ldm4(uint32_t* r, uint32_t addr) {
    asm volatile("ldmatrix.sync.aligned.m8n8.x4.shared.b16 {%0,%1,%2,%3}, [%4];"
        : "=r"(r[0]), "=r"(r[1]), "=r"(r[2]), "=r"(r[3]) : "r"(addr));
}
__device__ __forceinline__ void mma16816(float* d, const uint32_t* a, const uint32_t* b) {
    asm volatile("mma.sync.aligned.m16n8k16.row.col.f32.bf16.bf16.f32 "
        "{%0,%1,%2,%3}, {%4,%5,%6,%7}, {%8,%9}, {%0,%1,%2,%3};"
        : "+f"(d[0]), "+f"(d[1]), "+f"(d[2]), "+f"(d[3])
        : "r"(a[0]), "r"(a[1]), "r"(a[2]), "r"(a[3]), "r"(b[0]), "r"(b[1]));
}

// ---------------------------------------------------------------------------
// LayerNorm (affine, eps=1e-5) + ReLU, one block per row of 1024
// ---------------------------------------------------------------------------
__global__ void ln_relu_kernel(const float* __restrict__ in,
                               const float* __restrict__ gamma,
                               const float* __restrict__ beta,
                               float* __restrict__ out) {
    int row = blockIdx.x;
    int tid = threadIdx.x;
    const float* p = in + (size_t)row * DD + tid * 4;
    float4 xv = *(const float4*)p;

    float s  = xv.x + xv.y + xv.z + xv.w;
    float ss = xv.x*xv.x + xv.y*xv.y + xv.z*xv.z + xv.w*xv.w;
    #pragma unroll
    for (int off = 16; off > 0; off >>= 1) {
        s  += __shfl_xor_sync(0xffffffffu, s,  off);
        ss += __shfl_xor_sync(0xffffffffu, ss, off);
    }
    __shared__ float sbuf[8], ssbuf[8];
    __shared__ float smean, sinv;
    int lane = tid & 31, warp = tid >> 5;
    if (lane == 0) { sbuf[warp] = s; ssbuf[warp] = ss; }
    __syncthreads();
    if (tid == 0) {
        float ts = 0.f, tss = 0.f;
        #pragma unroll
        for (int i = 0; i < 8; i++) { ts += sbuf[i]; tss += ssbuf[i]; }
        float mean = ts * (1.0f / DD);
        float var  = tss * (1.0f / DD) - mean * mean;
        smean = mean;
        sinv  = rsqrtf(var + 1e-5f);
    }
    __syncthreads();
    float m = smean, inv = sinv;

    int c = tid * 4;
    float4 g4 = *(const float4*)(gamma + c);
    float4 b4 = *(const float4*)(beta  + c);
    float4 o;
    o.x = fmaxf(0.f, (xv.x - m) * inv * g4.x + b4.x);
    o.y = fmaxf(0.f, (xv.y - m) * inv * g4.y + b4.y);
    o.z = fmaxf(0.f, (xv.z - m) * inv * g4.z + b4.z);
    o.w = fmaxf(0.f, (xv.w - m) * inv * g4.w + b4.w);
    *(float4*)(out + (size_t)row * DD + c) = o;
}

// ---------------------------------------------------------------------------
// Split fp32 -> bf16 hi + bf16 lo (elementwise)
// ---------------------------------------------------------------------------
__global__ void split_kernel(const float* __restrict__ in,
                             __nv_bfloat16* __restrict__ hi,
                             __nv_bfloat16* __restrict__ lo) {
    int i = blockIdx.x * blockDim.x + threadIdx.x;   // float4 index
    float4 v = ((const float4*)in)[i];
    __nv_bfloat16 hx = __float2bfloat16_rn(v.x);
    __nv_bfloat16 hy = __float2bfloat16_rn(v.y);
    __nv_bfloat16 hz = __float2bfloat16_rn(v.z);
    __nv_bfloat16 hw = __float2bfloat16_rn(v.w);
    __nv_bfloat162 h0; h0.x = hx; h0.y = hy;
    __nv_bfloat162 h1; h1.x = hz; h1.y = hw;
    __nv_bfloat162 l0, l1;
    l0.x = __float2bfloat16_rn(v.x - __bfloat162float(hx));
    l0.y = __float2bfloat16_rn(v.y - __bfloat162float(hy));
    l1.x = __float2bfloat16_rn(v.z - __bfloat162float(hz));
    l1.y = __float2bfloat16_rn(v.w - __bfloat162float(hw));
    ((__nv_bfloat162*)hi)[2 * i]     = h0;
    ((__nv_bfloat162*)hi)[2 * i + 1] = h1;
    ((__nv_bfloat162*)lo)[2 * i]     = l0;
    ((__nv_bfloat162*)lo)[2 * i + 1] = l1;
}

// ---------------------------------------------------------------------------
// Transpose + split: W[K=1024, N=1024] fp32 -> Wt_hi/Wt_lo [N, K] bf16
// ---------------------------------------------------------------------------
__global__ void transpose_split_kernel(const float* __restrict__ W,
                                       __nv_bfloat16* __restrict__ hi,
                                       __nv_bfloat16* __restrict__ lo) {
    __shared__ float tile[32][33];
    int tx = threadIdx.x, ty = threadIdx.y;          // 32 x 8
    int n0 = blockIdx.x * 32, k0 = blockIdx.y * 32;
    #pragma unroll
    for (int i = 0; i < 4; i++) {
        int kr = ty + i * 8;
        tile[kr][tx] = W[(size_t)(k0 + kr) * DD + n0 + tx];
    }
    __syncthreads();
    #pragma unroll
    for (int i = 0; i < 4; i++) {
        int nr = ty + i * 8;
        float v = tile[tx][nr];
        __nv_bfloat16 h = __float2bfloat16_rn(v);
        __nv_bfloat16 l = __float2bfloat16_rn(v - __bfloat162float(h));
        hi[(size_t)(n0 + nr) * DD + k0 + tx] = h;
        lo[(size_t)(n0 + nr) * DD + k0 + tx] = l;
    }
}

// ---------------------------------------------------------------------------
// HMMA GEMM: C[M,1024] = A[M,1024] @ Wt^T (+ bias, + res)
// A: hi/lo bf16 [M,K] row-major; Wt: hi/lo bf16 [N,K] row-major.
// 3-term Markidis: ah*bh + ah*bl + al*bh (fp32 accumulate).
// CTA 128x128, BK=64, cp.async double-buffered smem, 8 warps (2M x 4N),
// warp tile 64x32 via mma.m16n8k16, ldmatrix with SW128 swizzle.
// Tiles in smem: 0=Ahi 1=Alo 2=Bhi 3=Blo, each 128 rows x 128 bytes.
// ---------------------------------------------------------------------------
#define GT_TILE 16384
#define GT_OFF(buf, which) (((which) * 2 + (buf)) * GT_TILE)
#define GT_SMEM (8 * GT_TILE)                       // 131072

struct GPtrs { const char *ahi, *alo, *bhi, *blo; };

__device__ __forceinline__ void gt_load_chunk(uint32_t sb, char* smem, int buf,
                                              const GPtrs& g, int chunk, int tid) {
    size_t kbyte = (size_t)chunk * 128;
    const char* gp[4] = {g.ahi, g.alo, g.bhi, g.blo};
    #pragma unroll
    for (int t = 0; t < 4; t++) {
        uint32_t base = sb + GT_OFF(buf, t);
        const char* src = gp[t];
        #pragma unroll
        for (int it = 0; it < 4; it++) {
            int idx = tid + it * 256;               // 0..1023 16B chunks
            int r = idx >> 3;
            int c16 = idx & 7;
            uint32_t so = (uint32_t)(r * 128 + c16 * 16);
            uint32_t sw = so ^ ((so >> 3) & 0x70);
            cpasync16(base + sw, src + (size_t)r * 2048 + kbyte + c16 * 16);
        }
    }
}

__global__ void __launch_bounds__(256, 1)
gemm_hmma(const __nv_bfloat16* __restrict__ Ahi, const __nv_bfloat16* __restrict__ Alo,
          const __nv_bfloat16* __restrict__ Bhi, const __nv_bfloat16* __restrict__ Blo,
          const float* __restrict__ bias, const float* __restrict__ res,
          float* __restrict__ C) {
    extern __shared__ char smem[];
    uint32_t sb = smem_u32(smem);
    int tid = threadIdx.x;
    int lane = tid & 31;
    int wid = tid >> 5;
    int wm = wid & 1;                // 0..1 (M)
    int wn = wid >> 1;               // 0..3 (N)

    int n0 = blockIdx.x * 128;
    int m0 = blockIdx.y * 128;

    GPtrs g;
    g.ahi = (const char*)(Ahi + (size_t)m0 * DD);
    g.alo = (const char*)(Alo + (size_t)m0 * DD);
    g.bhi = (const char*)(Bhi + (size_t)n0 * DD);
    g.blo = (const char*)(Blo + (size_t)n0 * DD);

    float acc[4][4][4];
    #pragma unroll
    for (int i = 0; i < 4; i++)
        #pragma unroll
        for (int j = 0; j < 4; j++)
            #pragma unroll
            for (int r = 0; r < 4; r++) acc[i][j][r] = 0.f;

    // per-thread ldmatrix address components
    uint32_t aRow = (uint32_t)(wm * 64 + (lane & 15));     // + 16*i per mfrag
    uint32_t xorb = (uint32_t)((lane & 7) * 16);
    uint32_t aHi  = (uint32_t)(((lane >> 4) & 1) * 16);
    uint32_t bRow = (uint32_t)(wn * 32 + ((lane >> 4) & 1) * 8 + (lane & 7)); // +16*jp
    uint32_t bHi  = (uint32_t)(((lane >> 3) & 1) * 16);

    gt_load_chunk(sb, smem, 0, g, 0, tid);
    CP_COMMIT();

    #pragma unroll 1
    for (int c = 0; c < 16; c++) {
        int buf = c & 1;
        if (c < 15) {
            gt_load_chunk(sb, smem, buf ^ 1, g, c + 1, tid);
            CP_COMMIT();
            CP_WAIT(1);
        } else {
            CP_WAIT(0);
        }
        __syncthreads();

        uint32_t tAh = sb + GT_OFF(buf, 0);
        uint32_t tAl = sb + GT_OFF(buf, 1);
        uint32_t tBh = sb + GT_OFF(buf, 2);
        uint32_t tBl = sb + GT_OFF(buf, 3);

        #pragma unroll
        for (int ks = 0; ks < 4; ks++) {
            uint32_t ka = ((uint32_t)(ks * 32) + aHi) ^ xorb;
            uint32_t kb = ((uint32_t)(ks * 32) + bHi) ^ xorb;

            uint32_t Ah[4][4], Al[4][4], Bh[2][4], Bl[2][4];
            #pragma unroll
            for (int i = 0; i < 4; i++) {
                uint32_t ro = (aRow + 16 * i) * 128;
                ldm4(Ah[i], tAh + ro + ka);
                ldm4(Al[i], tAl + ro + ka);
            }
            #pragma unroll
            for (int jp = 0; jp < 2; jp++) {
                uint32_t ro = (bRow + 16 * jp) * 128;
                ldm4(Bh[jp], tBh + ro + kb);
                ldm4(Bl[jp], tBl + ro + kb);
            }
            #pragma unroll
            for (int i = 0; i < 4; i++) {
                #pragma unroll
                for (int j = 0; j < 4; j++) {
                    const uint32_t* bh = &Bh[j >> 1][(j & 1) * 2];
                    const uint32_t* bl = &Bl[j >> 1][(j & 1) * 2];
                    mma16816(acc[i][j], Ah[i], bh);
                    mma16816(acc[i][j], Ah[i], bl);
                    mma16816(acc[i][j], Al[i], bh);
                }
            }
        }
        __syncthreads();
    }

    // epilogue: direct fragment stores with bias (+res)
    int rbase = m0 + wm * 64 + (lane >> 2);
    int cbase = n0 + wn * 32 + (lane & 3) * 2;
    #pragma unroll
    for (int j = 0; j < 4; j++) {
        int cc = cbase + 8 * j;
        float2 b2 = *(const float2*)(bias + cc);
        #pragma unroll
        for (int i = 0; i < 4; i++) {
            int r = rbase + 16 * i;
            float2 o0 = {acc[i][j][0] + b2.x, acc[i][j][1] + b2.y};
            float2 o1 = {acc[i][j][2] + b2.x, acc[i][j][3] + b2.y};
            size_t off0 = (size_t)r * DD + cc;
            size_t off1 = (size_t)(r + 8) * DD + cc;
            if (res) {
                float2 r0 = *(const float2*)(res + off0);
                float2 r1 = *(const float2*)(res + off1);
                o0.x += r0.x; o0.y += r0.y;
                o1.x += r1.x; o1.y += r1.y;
            }
            *(float2*)(C + off0) = o0;
            *(float2*)(C + off1) = o1;
        }
    }
}

// ---------------------------------------------------------------------------
// Scores: S[bh, t, T] = 0.125 * sum_d Q[b,t,h,d] * K[b,T,h,d]
// ---------------------------------------------------------------------------
__global__ void __launch_bounds__(256, 2)
scores_kernel(const float* __restrict__ Q, const float* __restrict__ Kmat,
              float* __restrict__ S) {
    __shared__ float Qs[64][68];
    __shared__ float Ks[64][68];

    int tid = threadIdx.x;
    int bh = blockIdx.z;
    int b = bh >> 4, h = bh & 15;
    int t0 = blockIdx.y * 64;
    int T0 = blockIdx.x * 64;

    const float* qb = Q    + (size_t)b * TQ * DD + h * DK;
    const float* kb = Kmat + (size_t)b * TK * DD + h * DK;

    #pragma unroll
    for (int it = 0; it < 4; it++) {
        int idx = tid + it * 256;
        int r = idx >> 4;
        int c = (idx & 15) * 4;
        float4 qa = *(const float4*)(qb + (size_t)(t0 + r) * DD + c);
        float4 ka = *(const float4*)(kb + (size_t)(T0 + r) * DD + c);
        Qs[r][c] = qa.x; Qs[r][c+1] = qa.y; Qs[r][c+2] = qa.z; Qs[r][c+3] = qa.w;
        Ks[r][c] = ka.x; Ks[r][c+1] = ka.y; Ks[r][c+2] = ka.z; Ks[r][c+3] = ka.w;
    }
    __syncthreads();

    int tx = (tid & 15) * 4, ty = (tid >> 4) * 4;
    float acc[4][4];
    #pragma unroll
    for (int i = 0; i < 4; i++)
        #pragma unroll
        for (int j = 0; j < 4; j++) acc[i][j] = 0.f;

    #pragma unroll 8
    for (int d = 0; d < 64; d++) {
        float a[4], bv[4];
        #pragma unroll
        for (int i = 0; i < 4; i++) a[i]  = Qs[ty + i][d];
        #pragma unroll
        for (int j = 0; j < 4; j++) bv[j] = Ks[tx + j][d];
        #pragma unroll
        for (int i = 0; i < 4; i++)
            #pragma unroll
            for (int j = 0; j < 4; j++)
                acc[i][j] = fmaf(a[i], bv[j], acc[i][j]);
    }

    float* out = S + ((size_t)bh * TQ) * TK;
    #pragma unroll
    for (int i = 0; i < 4; i++) {
        size_t off = (size_t)(t0 + ty + i) * TK + T0 + tx;
        #pragma unroll
        for (int j = 0; j < 4; j++)
            out[off + j] = acc[i][j] * 0.125f;
    }
}

// ---------------------------------------------------------------------------
// Masked softmax over rows of 1024 (in-place). mask [B, TK] int32.
// ---------------------------------------------------------------------------
__global__ void softmax_mask_kernel(float* __restrict__ S,
                                    const int* __restrict__ mask) {
    int row = blockIdx.x;
    int b = row >> 14;
    float* p = S + (size_t)row * TK;
    const int* mrow = mask + (size_t)b * TK;

    int c = threadIdx.x * 4;
    float4 v4 = *(const float4*)(p + c);
    int4  m4 = *(const int4*)(mrow + c);
    float v[4] = {v4.x, v4.y, v4.z, v4.w};
    if (!m4.x) v[0] = -1e30f;
    if (!m4.y) v[1] = -1e30f;
    if (!m4.z) v[2] = -1e30f;
    if (!m4.w) v[3] = -1e30f;

    float mx = fmaxf(fmaxf(v[0], v[1]), fmaxf(v[2], v[3]));
    #pragma unroll
    for (int off = 16; off > 0; off >>= 1)
        mx = fmaxf(mx, __shfl_xor_sync(0xffffffffu, mx, off));
    __shared__ float mbuf[8], sbuf[8];
    __shared__ float smax, ssum;
    int lane = threadIdx.x & 31, warp = threadIdx.x >> 5;
    if (lane == 0) mbuf[warp] = mx;
    __syncthreads();
    if (threadIdx.x == 0) {
        float m = mbuf[0];
        #pragma unroll
        for (int i = 1; i < 8; i++) m = fmaxf(m, mbuf[i]);
        smax = m;
    }
    __syncthreads();
    float m = smax;

    float e[4], s = 0.f;
    #pragma unroll
    for (int t = 0; t < 4; t++) { e[t] = __expf(v[t] - m); s += e[t]; }
    #pragma unroll
    for (int off = 16; off > 0; off >>= 1)
        s += __shfl_xor_sync(0xffffffffu, s, off);
    if (lane == 0) sbuf[warp] = s;
    __syncthreads();
    if (threadIdx.x == 0) {
        float ts = 0.f;
        #pragma unroll
        for (int i = 0; i < 8; i++) ts += sbuf[i];
        ssum = ts;
    }
    __syncthreads();
    float rinv = 1.0f / ssum;

    float4 o = {e[0] * rinv, e[1] * rinv, e[2] * rinv, e[3] * rinv};
    *(float4*)(p + c) = o;
}

// ---------------------------------------------------------------------------
// attn[b,t,h,:] = sum_T W[bh,t,T] * V[b,T,h,:]
// ---------------------------------------------------------------------------
__global__ void __launch_bounds__(256, 2)
attnv_kernel(const float* __restrict__ W, const float* __restrict__ V,
             float* __restrict__ out) {
    __shared__ float Ws[64][33];
    __shared__ float Vs[32][68];

    int tid = threadIdx.x;
    int bh = blockIdx.z;
    int b = bh >> 4, h = bh & 15;
    int t0 = blockIdx.y * 64;

    const float* Wbase = W + ((size_t)bh * TQ) * TK;
    const float* Vbase = V + (size_t)b * TK * DD + h * DV;

    int tx = (tid & 15) * 4, ty = (tid >> 4) * 4;
    float acc[4][4];
    #pragma unroll
    for (int i = 0; i < 4; i++)
        #pragma unroll
        for (int j = 0; j < 4; j++) acc[i][j] = 0.f;

    for (int T0 = 0; T0 < TK; T0 += 32) {
        #pragma unroll
        for (int it = 0; it < 2; it++) {
            int idx = tid + it * 256;
            int wr = idx >> 3, wc = (idx & 7) * 4;
            float4 w4 = *(const float4*)(Wbase + (size_t)(t0 + wr) * TK + T0 + wc);
            Ws[wr][wc] = w4.x; Ws[wr][wc+1] = w4.y; Ws[wr][wc+2] = w4.z; Ws[wr][wc+3] = w4.w;
            int vr = idx >> 4, vc = (idx & 15) * 4;
            float4 v4 = *(const float4*)(Vbase + (size_t)(T0 + vr) * DD + vc);
            Vs[vr][vc] = v4.x; Vs[vr][vc+1] = v4.y; Vs[vr][vc+2] = v4.z; Vs[vr][vc+3] = v4.w;
        }
        __syncthreads();

        #pragma unroll 8
        for (int kk = 0; kk < 32; kk++) {
            float a[4], bv[4];
            #pragma unroll
            for (int i = 0; i < 4; i++) a[i]  = Ws[ty + i][kk];
            #pragma unroll
            for (int j = 0; j < 4; j++) bv[j] = Vs[kk][tx + j];
            #pragma unroll
            for (int i = 0; i < 4; i++)
                #pragma unroll
                for (int j = 0; j < 4; j++)
                    acc[i][j] = fmaf(a[i], bv[j], acc[i][j]);
        }
        __syncthreads();
    }

    #pragma unroll
    for (int i = 0; i < 4; i++) {
        size_t off = (size_t)(b * TQ + t0 + ty + i) * DD + h * DV + tx;
        #pragma unroll
        for (int j = 0; j < 4; j++)
            out[off + j] = acc[i][j];
    }
}

// ---------------------------------------------------------------------------
// Launch
// ---------------------------------------------------------------------------
extern "C" void kernel_launch(void* const* d_in, const int* in_sizes, int n_in,
                              void* d_out, int out_size) {
    const float* x      = (const float*)d_in[0];
    const float* y      = (const float*)d_in[1];
    const int*   mask   = (const int*)d_in[2];
    const float* ln1_g  = (const float*)d_in[3];
    const float* ln1_b  = (const float*)d_in[4];
    const float* ln2_g  = (const float*)d_in[5];
    const float* ln2_b  = (const float*)d_in[6];
    const float* q_w    = (const float*)d_in[7];
    const float* q_b    = (const float*)d_in[8];
    const float* k_w    = (const float*)d_in[9];
    const float* k_b    = (const float*)d_in[10];
    const float* v_w    = (const float*)d_in[11];
    const float* v_b    = (const float*)d_in[12];
    const float* o_w    = (const float*)d_in[13];
    const float* o_b    = (const float*)d_in[14];
    const float* mln1_g = (const float*)d_in[15];
    const float* mln1_b = (const float*)d_in[16];
    const float* l1_w   = (const float*)d_in[17];
    const float* l1_b   = (const float*)d_in[18];
    const float* mln2_g = (const float*)d_in[19];
    const float* mln2_b = (const float*)d_in[20];
    const float* l2_w   = (const float*)d_in[21];
    const float* l2_b   = (const float*)d_in[22];
    float* out = (float*)d_out;

    float *x1, *y1, *q, *k, *v, *logits, *attn, *x2, *t1, *hbuf, *t2;
    __nv_bfloat16 *ahi, *alo, *bhi, *blo;
    cudaGetSymbolAddress((void**)&x1,     g_x1);
    cudaGetSymbolAddress((void**)&y1,     g_y1);
    cudaGetSymbolAddress((void**)&q,      g_q);
    cudaGetSymbolAddress((void**)&k,      g_k);
    cudaGetSymbolAddress((void**)&v,      g_v);
    cudaGetSymbolAddress((void**)&logits, g_logits);
    cudaGetSymbolAddress((void**)&attn,   g_attn);
    cudaGetSymbolAddress((void**)&x2,     g_x2);
    cudaGetSymbolAddress((void**)&t1,     g_t1);
    cudaGetSymbolAddress((void**)&hbuf,   g_h);
    cudaGetSymbolAddress((void**)&t2,     g_t2);
    cudaGetSymbolAddress((void**)&ahi,    g_ahi);
    cudaGetSymbolAddress((void**)&alo,    g_alo);
    cudaGetSymbolAddress((void**)&bhi,    g_bhi);
    cudaGetSymbolAddress((void**)&blo,    g_blo);

    cudaFuncSetAttribute(gemm_hmma, cudaFuncAttributeMaxDynamicSharedMemorySize, GT_SMEM);

    dim3 gemmGrid(8, 32);                       // N/128, M/128
    dim3 tGrid(32, 32);
    dim3 tBlock(32, 8);
    const int splitBlocks = (MROWS * DD) / 4 / 256;   // 4096

    // 1) pre-norms
    ln_relu_kernel<<<MROWS, 256>>>(x, ln1_g, ln1_b, x1);
    ln_relu_kernel<<<BB * TK, 256>>>(y, ln2_g, ln2_b, y1);

    // 2) projections (HMMA, bf16 hi/lo split)
    split_kernel<<<splitBlocks, 256>>>(x1, ahi, alo);
    transpose_split_kernel<<<tGrid, tBlock>>>(q_w, bhi, blo);
    gemm_hmma<<<gemmGrid, 256, GT_SMEM>>>(ahi, alo, bhi, blo, q_b, nullptr, q);

    split_kernel<<<splitBlocks, 256>>>(y1, ahi, alo);
    transpose_split_kernel<<<tGrid, tBlock>>>(k_w, bhi, blo);
    gemm_hmma<<<gemmGrid, 256, GT_SMEM>>>(ahi, alo, bhi, blo, k_b, nullptr, k);
    transpose_split_kernel<<<tGrid, tBlock>>>(v_w, bhi, blo);
    gemm_hmma<<<gemmGrid, 256, GT_SMEM>>>(ahi, alo, bhi, blo, v_b, nullptr, v);

    // 3) attention (fp32 for now)
    scores_kernel<<<dim3(TK / 64, TQ / 64, BH), 256>>>(q, k, logits);
    softmax_mask_kernel<<<BH * TQ, 256>>>(logits, mask);
    attnv_kernel<<<dim3(1, TQ / 64, BH), 256>>>(logits, v, attn);

    // 4) output proj + residual
    split_kernel<<<splitBlocks, 256>>>(attn, ahi, alo);
    transpose_split_kernel<<<tGrid, tBlock>>>(o_w, bhi, blo);
    gemm_hmma<<<gemmGrid, 256, GT_SMEM>>>(ahi, alo, bhi, blo, o_b, x, x2);

    // 5) MLP
    ln_relu_kernel<<<MROWS, 256>>>(x2, mln1_g, mln1_b, t1);
    split_kernel<<<splitBlocks, 256>>>(t1, ahi, alo);
    transpose_split_kernel<<<tGrid, tBlock>>>(l1_w, bhi, blo);
    gemm_hmma<<<gemmGrid, 256, GT_SMEM>>>(ahi, alo, bhi, blo, l1_b, nullptr, hbuf);

    ln_relu_kernel<<<MROWS, 256>>>(hbuf, mln2_g, mln2_b, t2);
    split_kernel<<<splitBlocks, 256>>>(t2, ahi, alo);
    transpose_split_kernel<<<tGrid, tBlock>>>(l2_w, bhi, blo);
    gemm_hmma<<<gemmGrid, 256, GT_SMEM>>>(ahi, alo, bhi, blo, l2_b, nullptr, out);
}

// round 5
// speedup vs baseline: 3.4826x; 2.0467x over previous
#include <cuda_runtime.h>
#include <cuda_bf16.h>
#include <math.h>
#include <stdint.h>

// ---------------------------------------------------------------------------
// Problem dims (fixed)
// ---------------------------------------------------------------------------
#define BB 4
#define TQ 1024
#define TK 1024
#define DD 1024
#define HH 16
#define DK 64
#define DV 64
#define MROWS (BB * TQ)          // 4096
#define BH (BB * HH)             // 64

// ---------------------------------------------------------------------------
// Scratch (device globals — no allocations allowed)
// ---------------------------------------------------------------------------
__device__ float g_x1[MROWS * DD];
__device__ float g_y1[BB * TK * DD];
__device__ float g_attn[MROWS * DD];
__device__ float g_x2 [MROWS * DD];
__device__ float g_t1 [MROWS * DD];
__device__ float g_h  [MROWS * DD];
__device__ float g_t2 [MROWS * DD];
// bf16 split buffers (GEMM A/B operands)
__device__ __nv_bfloat16 g_ahi[MROWS * DD];
__device__ __nv_bfloat16 g_alo[MROWS * DD];
__device__ __nv_bfloat16 g_bhi[DD * DD];
__device__ __nv_bfloat16 g_blo[DD * DD];
// bf16 q/k/v (written directly by GEMM epilogue)
__device__ __nv_bfloat16 g_qhi[MROWS * DD];
__device__ __nv_bfloat16 g_qlo[MROWS * DD];
__device__ __nv_bfloat16 g_khi[MROWS * DD];
__device__ __nv_bfloat16 g_klo[MROWS * DD];
__device__ __nv_bfloat16 g_vhi[MROWS * DD];
__device__ __nv_bfloat16 g_vlo[MROWS * DD];

// ---------------------------------------------------------------------------
// PTX helpers (sm_80+ baseline features only — no tcgen05 on plain sm_103)
// ---------------------------------------------------------------------------
__device__ __forceinline__ uint32_t smem_u32(const void* p) {
    uint32_t a;
    asm("{ .reg .u64 t; cvta.to.shared.u64 t, %1; cvt.u32.u64 %0, t; }" : "=r"(a) : "l"(p));
    return a;
}
__device__ __forceinline__ void cpasync16(uint32_t dst, const void* src) {
    asm volatile("cp.async.cg.shared.global [%0], [%1], 16;" :: "r"(dst), "l"(src) : "memory");
}
#define CP_COMMIT() asm volatile("cp.async.commit_group;" ::: "memory")
#define CP_WAIT(n)  asm volatile("cp.async.wait_group %0;" :: "n"(n) : "memory")

__device__ __forceinline__ void ldm4(uint32_t* r, uint32_t addr) {
    asm volatile("ldmatrix.sync.aligned.m8n8.x4.shared.b16 {%0,%1,%2,%3}, [%4];"
        : "=r"(r[0]), "=r"(r[1]), "=r"(r[2]), "=r"(r[3]) : "r"(addr));
}
__device__ __forceinline__ void ldm4t(uint32_t* r, uint32_t addr) {
    asm volatile("ldmatrix.sync.aligned.m8n8.x4.trans.shared.b16 {%0,%1,%2,%3}, [%4];"
        : "=r"(r[0]), "=r"(r[1]), "=r"(r[2]), "=r"(r[3]) : "r"(addr));
}
__device__ __forceinline__ void mma16816(float* d, const uint32_t* a, const uint32_t* b) {
    asm volatile("mma.sync.aligned.m16n8k16.row.col.f32.bf16.bf16.f32 "
        "{%0,%1,%2,%3}, {%4,%5,%6,%7}, {%8,%9}, {%0,%1,%2,%3};"
        : "+f"(d[0]), "+f"(d[1]), "+f"(d[2]), "+f"(d[3])
        : "r"(a[0]), "r"(a[1]), "r"(a[2]), "r"(a[3]), "r"(b[0]), "r"(b[1]));
}

// ---------------------------------------------------------------------------
// LayerNorm (affine, eps=1e-5) + ReLU, one block per row of 1024
// ---------------------------------------------------------------------------
__global__ void ln_relu_kernel(const float* __restrict__ in,
                               const float* __restrict__ gamma,
                               const float* __restrict__ beta,
                               float* __restrict__ out) {
    int row = blockIdx.x;
    int tid = threadIdx.x;
    const float* p = in + (size_t)row * DD + tid * 4;
    float4 xv = *(const float4*)p;

    float s  = xv.x + xv.y + xv.z + xv.w;
    float ss = xv.x*xv.x + xv.y*xv.y + xv.z*xv.z + xv.w*xv.w;
    #pragma unroll
    for (int off = 16; off > 0; off >>= 1) {
        s  += __shfl_xor_sync(0xffffffffu, s,  off);
        ss += __shfl_xor_sync(0xffffffffu, ss, off);
    }
    __shared__ float sbuf[8], ssbuf[8];
    __shared__ float smean, sinv;
    int lane = tid & 31, warp = tid >> 5;
    if (lane == 0) { sbuf[warp] = s; ssbuf[warp] = ss; }
    __syncthreads();
    if (tid == 0) {
        float ts = 0.f, tss = 0.f;
        #pragma unroll
        for (int i = 0; i < 8; i++) { ts += sbuf[i]; tss += ssbuf[i]; }
        float mean = ts * (1.0f / DD);
        float var  = tss * (1.0f / DD) - mean * mean;
        smean = mean;
        sinv  = rsqrtf(var + 1e-5f);
    }
    __syncthreads();
    float m = smean, inv = sinv;

    int c = tid * 4;
    float4 g4 = *(const float4*)(gamma + c);
    float4 b4 = *(const float4*)(beta  + c);
    float4 o;
    o.x = fmaxf(0.f, (xv.x - m) * inv * g4.x + b4.x);
    o.y = fmaxf(0.f, (xv.y - m) * inv * g4.y + b4.y);
    o.z = fmaxf(0.f, (xv.z - m) * inv * g4.z + b4.z);
    o.w = fmaxf(0.f, (xv.w - m) * inv * g4.w + b4.w);
    *(float4*)(out + (size_t)row * DD + c) = o;
}

// ---------------------------------------------------------------------------
// Split fp32 -> bf16 hi + bf16 lo (elementwise)
// ---------------------------------------------------------------------------
__global__ void split_kernel(const float* __restrict__ in,
                             __nv_bfloat16* __restrict__ hi,
                             __nv_bfloat16* __restrict__ lo) {
    int i = blockIdx.x * blockDim.x + threadIdx.x;   // float4 index
    float4 v = ((const float4*)in)[i];
    __nv_bfloat16 hx = __float2bfloat16_rn(v.x);
    __nv_bfloat16 hy = __float2bfloat16_rn(v.y);
    __nv_bfloat16 hz = __float2bfloat16_rn(v.z);
    __nv_bfloat16 hw = __float2bfloat16_rn(v.w);
    __nv_bfloat162 h0; h0.x = hx; h0.y = hy;
    __nv_bfloat162 h1; h1.x = hz; h1.y = hw;
    __nv_bfloat162 l0, l1;
    l0.x = __float2bfloat16_rn(v.x - __bfloat162float(hx));
    l0.y = __float2bfloat16_rn(v.y - __bfloat162float(hy));
    l1.x = __float2bfloat16_rn(v.z - __bfloat162float(hz));
    l1.y = __float2bfloat16_rn(v.w - __bfloat162float(hw));
    ((__nv_bfloat162*)hi)[2 * i]     = h0;
    ((__nv_bfloat162*)hi)[2 * i + 1] = h1;
    ((__nv_bfloat162*)lo)[2 * i]     = l0;
    ((__nv_bfloat162*)lo)[2 * i + 1] = l1;
}

// ---------------------------------------------------------------------------
// Transpose + split: W[K=1024, N=1024] fp32 -> Wt_hi/Wt_lo [N, K] bf16
// ---------------------------------------------------------------------------
__global__ void transpose_split_kernel(const float* __restrict__ W,
                                       __nv_bfloat16* __restrict__ hi,
                                       __nv_bfloat16* __restrict__ lo) {
    __shared__ float tile[32][33];
    int tx = threadIdx.x, ty = threadIdx.y;          // 32 x 8
    int n0 = blockIdx.x * 32, k0 = blockIdx.y * 32;
    #pragma unroll
    for (int i = 0; i < 4; i++) {
        int kr = ty + i * 8;
        tile[kr][tx] = W[(size_t)(k0 + kr) * DD + n0 + tx];
    }
    __syncthreads();
    #pragma unroll
    for (int i = 0; i < 4; i++) {
        int nr = ty + i * 8;
        float v = tile[tx][nr];
        __nv_bfloat16 h = __float2bfloat16_rn(v);
        __nv_bfloat16 l = __float2bfloat16_rn(v - __bfloat162float(h));
        hi[(size_t)(n0 + nr) * DD + k0 + tx] = h;
        lo[(size_t)(n0 + nr) * DD + k0 + tx] = l;
    }
}

// ---------------------------------------------------------------------------
// HMMA GEMM: C[M,1024] = A[M,1024] @ Wt^T (+ bias, + res)
// Output either fp32 (C) or bf16 hi/lo pair (Chi/Clo).
// ---------------------------------------------------------------------------
#define GT_TILE 16384
#define GT_OFF(buf, which) (((which) * 2 + (buf)) * GT_TILE)
#define GT_SMEM (8 * GT_TILE)                       // 131072

struct GPtrs { const char *ahi, *alo, *bhi, *blo; };

__device__ __forceinline__ void gt_load_chunk(uint32_t sb, int buf,
                                              const GPtrs& g, int chunk, int tid) {
    size_t kbyte = (size_t)chunk * 128;
    const char* gp[4] = {g.ahi, g.alo, g.bhi, g.blo};
    #pragma unroll
    for (int t = 0; t < 4; t++) {
        uint32_t base = sb + GT_OFF(buf, t);
        const char* src = gp[t];
        #pragma unroll
        for (int it = 0; it < 4; it++) {
            int idx = tid + it * 256;               // 0..1023 16B chunks
            int r = idx >> 3;
            int c16 = idx & 7;
            uint32_t so = (uint32_t)(r * 128 + c16 * 16);
            uint32_t sw = so ^ ((so >> 3) & 0x70);
            cpasync16(base + sw, src + (size_t)r * 2048 + kbyte + c16 * 16);
        }
    }
}

__global__ void __launch_bounds__(256, 1)
gemm_hmma(const __nv_bfloat16* __restrict__ Ahi, const __nv_bfloat16* __restrict__ Alo,
          const __nv_bfloat16* __restrict__ Bhi, const __nv_bfloat16* __restrict__ Blo,
          const float* __restrict__ bias, const float* __restrict__ res,
          float* __restrict__ C,
          __nv_bfloat16* __restrict__ Chi, __nv_bfloat16* __restrict__ Clo) {
    extern __shared__ char smem[];
    uint32_t sb = smem_u32(smem);
    int tid = threadIdx.x;
    int lane = tid & 31;
    int wid = tid >> 5;
    int wm = wid & 1;                // 0..1 (M)
    int wn = wid >> 1;               // 0..3 (N)

    int n0 = blockIdx.x * 128;
    int m0 = blockIdx.y * 128;

    GPtrs g;
    g.ahi = (const char*)(Ahi + (size_t)m0 * DD);
    g.alo = (const char*)(Alo + (size_t)m0 * DD);
    g.bhi = (const char*)(Bhi + (size_t)n0 * DD);
    g.blo = (const char*)(Blo + (size_t)n0 * DD);

    float acc[4][4][4];
    #pragma unroll
    for (int i = 0; i < 4; i++)
        #pragma unroll
        for (int j = 0; j < 4; j++)
            #pragma unroll
            for (int r = 0; r < 4; r++) acc[i][j][r] = 0.f;

    uint32_t aRow = (uint32_t)(wm * 64 + (lane & 15));
    uint32_t xorb = (uint32_t)((lane & 7) * 16);
    uint32_t aHi  = (uint32_t)(((lane >> 4) & 1) * 16);
    uint32_t bRow = (uint32_t)(wn * 32 + ((lane >> 4) & 1) * 8 + (lane & 7));
    uint32_t bHi  = (uint32_t)(((lane >> 3) & 1) * 16);

    gt_load_chunk(sb, 0, g, 0, tid);
    CP_COMMIT();

    #pragma unroll 1
    for (int c = 0; c < 16; c++) {
        int buf = c & 1;
        if (c < 15) {
            gt_load_chunk(sb, buf ^ 1, g, c + 1, tid);
            CP_COMMIT();
            CP_WAIT(1);
        } else {
            CP_WAIT(0);
        }
        __syncthreads();

        uint32_t tAh = sb + GT_OFF(buf, 0);
        uint32_t tAl = sb + GT_OFF(buf, 1);
        uint32_t tBh = sb + GT_OFF(buf, 2);
        uint32_t tBl = sb + GT_OFF(buf, 3);

        #pragma unroll
        for (int ks = 0; ks < 4; ks++) {
            uint32_t ka = ((uint32_t)(ks * 32) + aHi) ^ xorb;
            uint32_t kb = ((uint32_t)(ks * 32) + bHi) ^ xorb;

            uint32_t Ah[4][4], Al[4][4], Bh[2][4], Bl[2][4];
            #pragma unroll
            for (int i = 0; i < 4; i++) {
                uint32_t ro = (aRow + 16 * i) * 128;
                ldm4(Ah[i], tAh + ro + ka);
                ldm4(Al[i], tAl + ro + ka);
            }
            #pragma unroll
            for (int jp = 0; jp < 2; jp++) {
                uint32_t ro = (bRow + 16 * jp) * 128;
                ldm4(Bh[jp], tBh + ro + kb);
                ldm4(Bl[jp], tBl + ro + kb);
            }
            #pragma unroll
            for (int i = 0; i < 4; i++) {
                #pragma unroll
                for (int j = 0; j < 4; j++) {
                    const uint32_t* bh = &Bh[j >> 1][(j & 1) * 2];
                    const uint32_t* bl = &Bl[j >> 1][(j & 1) * 2];
                    mma16816(acc[i][j], Ah[i], bh);
                    mma16816(acc[i][j], Ah[i], bl);
                    mma16816(acc[i][j], Al[i], bh);
                }
            }
        }
        __syncthreads();
    }

    int rbase = m0 + wm * 64 + (lane >> 2);
    int cbase = n0 + wn * 32 + (lane & 3) * 2;
    #pragma unroll
    for (int j = 0; j < 4; j++) {
        int cc = cbase + 8 * j;
        float2 b2 = *(const float2*)(bias + cc);
        #pragma unroll
        for (int i = 0; i < 4; i++) {
            int r = rbase + 16 * i;
            float2 o0 = {acc[i][j][0] + b2.x, acc[i][j][1] + b2.y};
            float2 o1 = {acc[i][j][2] + b2.x, acc[i][j][3] + b2.y};
            size_t off0 = (size_t)r * DD + cc;
            size_t off1 = (size_t)(r + 8) * DD + cc;
            if (Chi) {
                __nv_bfloat162 h0 = __floats2bfloat162_rn(o0.x, o0.y);
                __nv_bfloat162 h1 = __floats2bfloat162_rn(o1.x, o1.y);
                __nv_bfloat162 l0 = __floats2bfloat162_rn(
                    o0.x - __bfloat162float(h0.x), o0.y - __bfloat162float(h0.y));
                __nv_bfloat162 l1 = __floats2bfloat162_rn(
                    o1.x - __bfloat162float(h1.x), o1.y - __bfloat162float(h1.y));
                *(__nv_bfloat162*)(Chi + off0) = h0;
                *(__nv_bfloat162*)(Chi + off1) = h1;
                *(__nv_bfloat162*)(Clo + off0) = l0;
                *(__nv_bfloat162*)(Clo + off1) = l1;
            } else {
                if (res) {
                    float2 r0 = *(const float2*)(res + off0);
                    float2 r1 = *(const float2*)(res + off1);
                    o0.x += r0.x; o0.y += r0.y;
                    o1.x += r1.x; o1.y += r1.y;
                }
                *(float2*)(C + off0) = o0;
                *(float2*)(C + off1) = o1;
            }
        }
    }
}

// ---------------------------------------------------------------------------
// Fused flash attention (bf16 HMMA, hi/lo 3-term for S and PV).
// Grid: (TQ/128 = 8, BH = 64), 256 threads (8 warps, 16 q-rows each).
// K/V chunks of 64 keys, cp.async double-buffered.
// smem: Qh(16K) Ql(16K) | 2 x [Kh Kl Vh Vl](32K each) | maskf 2x64 floats
// ---------------------------------------------------------------------------
#define FA_KBUF(buf) (32768 + (buf) * 32768)
#define FA_SMEM      (98304 + 512)

__global__ void __launch_bounds__(256, 1)
flash_kernel(const __nv_bfloat16* __restrict__ Qhi, const __nv_bfloat16* __restrict__ Qlo,
             const __nv_bfloat16* __restrict__ Khi, const __nv_bfloat16* __restrict__ Klo,
             const __nv_bfloat16* __restrict__ Vhi, const __nv_bfloat16* __restrict__ Vlo,
             const int* __restrict__ mask, float* __restrict__ Out) {
    extern __shared__ char smem[];
    uint32_t sb = smem_u32(smem);
    int tid = threadIdx.x;
    int lane = tid & 31, wid = tid >> 5;
    int qtile = blockIdx.x;
    int bh = blockIdx.y;
    int b = bh >> 4, h = bh & 15;

    size_t qrow0 = (size_t)b * TQ + (size_t)qtile * 128;
    size_t krow0 = (size_t)b * TK;
    uint32_t hbyte = (uint32_t)h * 128;        // 64 bf16 cols

    uint32_t sQh = sb, sQl = sb + 16384;
    float* mfbase = (float*)(smem + 98304);

    // Q tile loads (hi+lo): 128 rows x 128B each
    {
        const char* gh = (const char*)Qhi;
        const char* gl = (const char*)Qlo;
        #pragma unroll
        for (int it = 0; it < 4; it++) {
            int idx = tid + it * 256;          // 0..1023
            int r = idx >> 3, c16 = (idx & 7) * 16;
            uint32_t so = (uint32_t)(r * 128 + c16);
            uint32_t sw = so ^ ((so >> 3) & 0x70);
            size_t go = (qrow0 + r) * 2048 + hbyte + c16;
            cpasync16(sQh + sw, gh + go);
            cpasync16(sQl + sw, gl + go);
        }
    }

    const char* gK[2] = {(const char*)Khi, (const char*)Klo};
    const char* gV[2] = {(const char*)Vhi, (const char*)Vlo};

    // chunk 0 + commit (same group as Q)
    {
        uint32_t base = sb + FA_KBUF(0);
        #pragma unroll
        for (int t = 0; t < 4; t++) {
            const char* src = (t < 2) ? gK[t] : gV[t - 2];
            uint32_t tb = base + t * 8192;
            #pragma unroll
            for (int it = 0; it < 2; it++) {
                int idx = tid + it * 256;
                int r = idx >> 3, c16 = (idx & 7) * 16;
                uint32_t so = (uint32_t)(r * 128 + c16);
                uint32_t sw = so ^ ((so >> 3) & 0x70);
                cpasync16(tb + sw, src + (krow0 + r) * 2048 + hbyte + c16);
            }
        }
    }
    CP_COMMIT();
    if (tid < 64) mfbase[tid] = mask[(size_t)b * TK + tid] ? 1.f : 0.f;
    // chunk 1 + commit
    {
        uint32_t base = sb + FA_KBUF(1);
        #pragma unroll
        for (int t = 0; t < 4; t++) {
            const char* src = (t < 2) ? gK[t] : gV[t - 2];
            uint32_t tb = base + t * 8192;
            #pragma unroll
            for (int it = 0; it < 2; it++) {
                int idx = tid + it * 256;
                int r = idx >> 3, c16 = (idx & 7) * 16;
                uint32_t so = (uint32_t)(r * 128 + c16);
                uint32_t sw = so ^ ((so >> 3) & 0x70);
                cpasync16(tb + sw, src + (krow0 + 64 + r) * 2048 + hbyte + c16);
            }
        }
    }
    CP_COMMIT();
    if (tid < 64) mfbase[64 + tid] = mask[(size_t)b * TK + 64 + tid] ? 1.f : 0.f;

    uint32_t xorb = (uint32_t)((lane & 7) * 16);
    uint32_t aHi  = (uint32_t)(((lane >> 4) & 1) * 16);
    uint32_t kRowBase = 8 * ((lane >> 4) & 1) + (lane & 7);
    uint32_t kColHalf = 16 * ((lane >> 3) & 1);
    uint32_t vRowBase = 8 * ((lane >> 3) & 1) + (lane & 7);
    uint32_t vColHalf = 16 * ((lane >> 4) & 1);

    float O[8][4];
    #pragma unroll
    for (int f = 0; f < 8; f++)
        #pragma unroll
        for (int r = 0; r < 4; r++) O[f][r] = 0.f;
    float mrow0 = -INFINITY, mrow1 = -INFINITY;
    float lrow0 = 0.f, lrow1 = 0.f;
    uint32_t QhF[4][4], QlF[4][4];

    #pragma unroll 1
    for (int c = 0; c < 16; c++) {
        int buf = c & 1;
        if (c < 15) { CP_WAIT(1); } else { CP_WAIT(0); }
        __syncthreads();

        if (c == 0) {
            #pragma unroll
            for (int ks = 0; ks < 4; ks++) {
                uint32_t row = (uint32_t)(wid * 16 + (lane & 15));
                uint32_t col = ((uint32_t)(ks * 32) + aHi) ^ xorb;
                ldm4(QhF[ks], sQh + row * 128 + col);
                ldm4(QlF[ks], sQl + row * 128 + col);
            }
        }

        uint32_t sKh = sb + FA_KBUF(buf);
        uint32_t sKl = sKh + 8192;
        uint32_t sVh = sKh + 16384;
        uint32_t sVl = sKh + 24576;
        const float* mf = mfbase + buf * 64;

        // ---- S = Q K^T (3-term hi/lo)
        float S[8][4];
        #pragma unroll
        for (int n = 0; n < 8; n++)
            #pragma unroll
            for (int r = 0; r < 4; r++) S[n][r] = 0.f;

        #pragma unroll
        for (int ks = 0; ks < 4; ks++) {
            uint32_t col = ((uint32_t)(ks * 32) + kColHalf) ^ xorb;
            #pragma unroll
            for (int np = 0; np < 4; np++) {
                uint32_t KhF[4], KlF[4];
                uint32_t ro = (np * 16 + kRowBase) * 128;
                ldm4(KhF, sKh + ro + col);
                ldm4(KlF, sKl + ro + col);
                mma16816(S[np*2],   QhF[ks], KhF);
                mma16816(S[np*2],   QhF[ks], KlF);
                mma16816(S[np*2],   QlF[ks], KhF);
                mma16816(S[np*2+1], QhF[ks], KhF + 2);
                mma16816(S[np*2+1], QhF[ks], KlF + 2);
                mma16816(S[np*2+1], QlF[ks], KhF + 2);
            }
        }

        // ---- mask + scale (set to -1e30, matching reference where())
        #pragma unroll
        for (int n = 0; n < 8; n++) {
            int j = 8 * n + (lane & 3) * 2;
            float mk0 = mf[j], mk1 = mf[j + 1];
            S[n][0] = (mk0 != 0.f) ? S[n][0] * 0.125f : -1e30f;
            S[n][1] = (mk1 != 0.f) ? S[n][1] * 0.125f : -1e30f;
            S[n][2] = (mk0 != 0.f) ? S[n][2] * 0.125f : -1e30f;
            S[n][3] = (mk1 != 0.f) ? S[n][3] * 0.125f : -1e30f;
        }

        // ---- online softmax (rows r = lane>>2 and r+8)
        float cm0 = -INFINITY, cm1 = -INFINITY;
        #pragma unroll
        for (int n = 0; n < 8; n++) {
            cm0 = fmaxf(cm0, fmaxf(S[n][0], S[n][1]));
            cm1 = fmaxf(cm1, fmaxf(S[n][2], S[n][3]));
        }
        cm0 = fmaxf(cm0, __shfl_xor_sync(0xffffffffu, cm0, 1));
        cm0 = fmaxf(cm0, __shfl_xor_sync(0xffffffffu, cm0, 2));
        cm1 = fmaxf(cm1, __shfl_xor_sync(0xffffffffu, cm1, 1));
        cm1 = fmaxf(cm1, __shfl_xor_sync(0xffffffffu, cm1, 2));

        float mn0 = fmaxf(mrow0, cm0);
        float mn1 = fmaxf(mrow1, cm1);
        float al0 = __expf(mrow0 - mn0);
        float al1 = __expf(mrow1 - mn1);
        mrow0 = mn0; mrow1 = mn1;

        uint32_t Phi[4][4], Plo[4][4];
        float sum0 = 0.f, sum1 = 0.f;
        #pragma unroll
        for (int n = 0; n < 8; n++) {
            float p0 = __expf(S[n][0] - mn0);
            float p1 = __expf(S[n][1] - mn0);
            float p2 = __expf(S[n][2] - mn1);
            float p3 = __expf(S[n][3] - mn1);
            sum0 += p0 + p1;
            sum1 += p2 + p3;
            __nv_bfloat162 h01 = __floats2bfloat162_rn(p0, p1);
            __nv_bfloat162 h23 = __floats2bfloat162_rn(p2, p3);
            __nv_bfloat162 l01 = __floats2bfloat162_rn(
                p0 - __bfloat162float(h01.x), p1 - __bfloat162float(h01.y));
            __nv_bfloat162 l23 = __floats2bfloat162_rn(
                p2 - __bfloat162float(h23.x), p3 - __bfloat162float(h23.y));
            int kk = n >> 1, base = (n & 1) * 2;
            Phi[kk][base]     = *(uint32_t*)&h01;
            Phi[kk][base + 1] = *(uint32_t*)&h23;
            Plo[kk][base]     = *(uint32_t*)&l01;
            Plo[kk][base + 1] = *(uint32_t*)&l23;
        }
        sum0 += __shfl_xor_sync(0xffffffffu, sum0, 1);
        sum0 += __shfl_xor_sync(0xffffffffu, sum0, 2);
        sum1 += __shfl_xor_sync(0xffffffffu, sum1, 1);
        sum1 += __shfl_xor_sync(0xffffffffu, sum1, 2);
        lrow0 = lrow0 * al0 + sum0;
        lrow1 = lrow1 * al1 + sum1;
        #pragma unroll
        for (int f = 0; f < 8; f++) {
            O[f][0] *= al0; O[f][1] *= al0;
            O[f][2] *= al1; O[f][3] *= al1;
        }

        // ---- O += P V (3-term hi/lo, V via ldmatrix.trans)
        #pragma unroll
        for (int ks = 0; ks < 4; ks++) {
            uint32_t ro = (ks * 16 + vRowBase) * 128;
            #pragma unroll
            for (int dp = 0; dp < 4; dp++) {
                uint32_t col = ((uint32_t)(dp * 32) + vColHalf) ^ xorb;
                uint32_t VhF[4], VlF[4];
                ldm4t(VhF, sVh + ro + col);
                ldm4t(VlF, sVl + ro + col);
                mma16816(O[dp*2],   Phi[ks], VhF);
                mma16816(O[dp*2],   Phi[ks], VlF);
                mma16816(O[dp*2],   Plo[ks], VhF);
                mma16816(O[dp*2+1], Phi[ks], VhF + 2);
                mma16816(O[dp*2+1], Phi[ks], VlF + 2);
                mma16816(O[dp*2+1], Plo[ks], VhF + 2);
            }
        }

        __syncthreads();
        if (c < 14) {
            int T0 = (c + 2) * 64;
            uint32_t base = sb + FA_KBUF(buf);
            #pragma unroll
            for (int t = 0; t < 4; t++) {
                const char* src = (t < 2) ? gK[t] : gV[t - 2];
                uint32_t tb = base + t * 8192;
                #pragma unroll
                for (int it = 0; it < 2; it++) {
                    int idx = tid + it * 256;
                    int r = idx >> 3, c16 = (idx & 7) * 16;
                    uint32_t so = (uint32_t)(r * 128 + c16);
                    uint32_t sw = so ^ ((so >> 3) & 0x70);
                    cpasync16(tb + sw, src + (krow0 + T0 + r) * 2048 + hbyte + c16);
                }
            }
            CP_COMMIT();
            if (tid < 64)
                mfbase[buf * 64 + tid] = mask[(size_t)b * TK + T0 + tid] ? 1.f : 0.f;
        }
    }

    // ---- finalize + write
    float rinv0 = 1.f / lrow0;
    float rinv1 = 1.f / lrow1;
    int grow = (int)qrow0 + wid * 16 + (lane >> 2);
    int col0 = h * 64 + (lane & 3) * 2;
    #pragma unroll
    for (int f = 0; f < 8; f++) {
        int cc = col0 + 8 * f;
        float2 o0 = {O[f][0] * rinv0, O[f][1] * rinv0};
        float2 o1 = {O[f][2] * rinv1, O[f][3] * rinv1};
        *(float2*)(Out + (size_t)grow * DD + cc) = o0;
        *(float2*)(Out + (size_t)(grow + 8) * DD + cc) = o1;
    }
}

// ---------------------------------------------------------------------------
// Launch
// ---------------------------------------------------------------------------
extern "C" void kernel_launch(void* const* d_in, const int* in_sizes, int n_in,
                              void* d_out, int out_size) {
    const float* x      = (const float*)d_in[0];
    const float* y      = (const float*)d_in[1];
    const int*   mask   = (const int*)d_in[2];
    const float* ln1_g  = (const float*)d_in[3];
    const float* ln1_b  = (const float*)d_in[4];
    const float* ln2_g  = (const float*)d_in[5];
    const float* ln2_b  = (const float*)d_in[6];
    const float* q_w    = (const float*)d_in[7];
    const float* q_b    = (const float*)d_in[8];
    const float* k_w    = (const float*)d_in[9];
    const float* k_b    = (const float*)d_in[10];
    const float* v_w    = (const float*)d_in[11];
    const float* v_b    = (const float*)d_in[12];
    const float* o_w    = (const float*)d_in[13];
    const float* o_b    = (const float*)d_in[14];
    const float* mln1_g = (const float*)d_in[15];
    const float* mln1_b = (const float*)d_in[16];
    const float* l1_w   = (const float*)d_in[17];
    const float* l1_b   = (const float*)d_in[18];
    const float* mln2_g = (const float*)d_in[19];
    const float* mln2_b = (const float*)d_in[20];
    const float* l2_w   = (const float*)d_in[21];
    const float* l2_b   = (const float*)d_in[22];
    float* out = (float*)d_out;

    float *x1, *y1, *attn, *x2, *t1, *hbuf, *t2;
    __nv_bfloat16 *ahi, *alo, *bhi, *blo;
    __nv_bfloat16 *qhi, *qlo, *khi, *klo, *vhi, *vlo;
    cudaGetSymbolAddress((void**)&x1,   g_x1);
    cudaGetSymbolAddress((void**)&y1,   g_y1);
    cudaGetSymbolAddress((void**)&attn, g_attn);
    cudaGetSymbolAddress((void**)&x2,   g_x2);
    cudaGetSymbolAddress((void**)&t1,   g_t1);
    cudaGetSymbolAddress((void**)&hbuf, g_h);
    cudaGetSymbolAddress((void**)&t2,   g_t2);
    cudaGetSymbolAddress((void**)&ahi,  g_ahi);
    cudaGetSymbolAddress((void**)&alo,  g_alo);
    cudaGetSymbolAddress((void**)&bhi,  g_bhi);
    cudaGetSymbolAddress((void**)&blo,  g_blo);
    cudaGetSymbolAddress((void**)&qhi,  g_qhi);
    cudaGetSymbolAddress((void**)&qlo,  g_qlo);
    cudaGetSymbolAddress((void**)&khi,  g_khi);
    cudaGetSymbolAddress((void**)&klo,  g_klo);
    cudaGetSymbolAddress((void**)&vhi,  g_vhi);
    cudaGetSymbolAddress((void**)&vlo,  g_vlo);

    cudaFuncSetAttribute(gemm_hmma, cudaFuncAttributeMaxDynamicSharedMemorySize, GT_SMEM);
    cudaFuncSetAttribute(flash_kernel, cudaFuncAttributeMaxDynamicSharedMemorySize, FA_SMEM);

    dim3 gemmGrid(8, 32);
    dim3 tGrid(32, 32);
    dim3 tBlock(32, 8);
    const int splitBlocks = (MROWS * DD) / 4 / 256;   // 4096

    // 1) pre-norms
    ln_relu_kernel<<<MROWS, 256>>>(x, ln1_g, ln1_b, x1);
    ln_relu_kernel<<<BB * TK, 256>>>(y, ln2_g, ln2_b, y1);

    // 2) q/k/v projections -> bf16 hi/lo directly
    split_kernel<<<splitBlocks, 256>>>(x1, ahi, alo);
    transpose_split_kernel<<<tGrid, tBlock>>>(q_w, bhi, blo);
    gemm_hmma<<<gemmGrid, 256, GT_SMEM>>>(ahi, alo, bhi, blo, q_b, nullptr,
                                          nullptr, qhi, qlo);
    split_kernel<<<splitBlocks, 256>>>(y1, ahi, alo);
    transpose_split_kernel<<<tGrid, tBlock>>>(k_w, bhi, blo);
    gemm_hmma<<<gemmGrid, 256, GT_SMEM>>>(ahi, alo, bhi, blo, k_b, nullptr,
                                          nullptr, khi, klo);
    transpose_split_kernel<<<tGrid, tBlock>>>(v_w, bhi, blo);
    gemm_hmma<<<gemmGrid, 256, GT_SMEM>>>(ahi, alo, bhi, blo, v_b, nullptr,
                                          nullptr, vhi, vlo);

    // 3) fused flash attention
    flash_kernel<<<dim3(8, BH), 256, FA_SMEM>>>(qhi, qlo, khi, klo, vhi, vlo,
                                                mask, attn);

    // 4) output proj + residual
    split_kernel<<<splitBlocks, 256>>>(attn, ahi, alo);
    transpose_split_kernel<<<tGrid, tBlock>>>(o_w, bhi, blo);
    gemm_hmma<<<gemmGrid, 256, GT_SMEM>>>(ahi, alo, bhi, blo, o_b, x,
                                          x2, nullptr, nullptr);

    // 5) MLP
    ln_relu_kernel<<<MROWS, 256>>>(x2, mln1_g, mln1_b, t1);
    split_kernel<<<splitBlocks, 256>>>(t1, ahi, alo);
    transpose_split_kernel<<<tGrid, tBlock>>>(l1_w, bhi, blo);
    gemm_hmma<<<gemmGrid, 256, GT_SMEM>>>(ahi, alo, bhi, blo, l1_b, nullptr,
                                          hbuf, nullptr, nullptr);

    ln_relu_kernel<<<MROWS, 256>>>(hbuf, mln2_g, mln2_b, t2);
    split_kernel<<<splitBlocks, 256>>>(t2, ahi, alo);
    transpose_split_kernel<<<tGrid, tBlock>>>(l2_w, bhi, blo);
    gemm_hmma<<<gemmGrid, 256, GT_SMEM>>>(ahi, alo, bhi, blo, l2_b, nullptr,
                                          out, nullptr, nullptr);
}

// round 6
// speedup vs baseline: 3.6506x; 1.0482x over previous
#include <cuda_runtime.h>
#include <cuda_bf16.h>
#include <math.h>
#include <stdint.h>

// ---------------------------------------------------------------------------
// Problem dims (fixed)
// ---------------------------------------------------------------------------
#define BB 4
#define TQ 1024
#define TK 1024
#define DD 1024
#define HH 16
#define DK 64
#define DV 64
#define MROWS (BB * TQ)          // 4096
#define BH (BB * HH)             // 64

// ---------------------------------------------------------------------------
// Scratch (device globals — no allocations allowed)
// ---------------------------------------------------------------------------
__device__ float g_x2 [MROWS * DD];
__device__ float g_h  [MROWS * DD];
// bf16 hi/lo activation buffers
__device__ __nv_bfloat16 g_xhi[MROWS * DD];   // ln1(x) / mln1(x2) reuse
__device__ __nv_bfloat16 g_xlo[MROWS * DD];
__device__ __nv_bfloat16 g_yhi[MROWS * DD];   // ln2(y) / mln2(h) reuse
__device__ __nv_bfloat16 g_ylo[MROWS * DD];
__device__ __nv_bfloat16 g_phi[MROWS * DD];   // flash output
__device__ __nv_bfloat16 g_plo[MROWS * DD];
// weight (transposed) buffers
__device__ __nv_bfloat16 g_bhi[DD * DD];
__device__ __nv_bfloat16 g_blo[DD * DD];
// q/k/v bf16 (written directly by GEMM epilogue)
__device__ __nv_bfloat16 g_qhi[MROWS * DD];
__device__ __nv_bfloat16 g_qlo[MROWS * DD];
__device__ __nv_bfloat16 g_khi[MROWS * DD];
__device__ __nv_bfloat16 g_klo[MROWS * DD];
__device__ __nv_bfloat16 g_vhi[MROWS * DD];
__device__ __nv_bfloat16 g_vlo[MROWS * DD];

// ---------------------------------------------------------------------------
// PTX helpers (sm_80+ baseline features only)
// ---------------------------------------------------------------------------
__device__ __forceinline__ uint32_t smem_u32(const void* p) {
    uint32_t a;
    asm("{ .reg .u64 t; cvta.to.shared.u64 t, %1; cvt.u32.u64 %0, t; }" : "=r"(a) : "l"(p));
    return a;
}
__device__ __forceinline__ void cpasync16(uint32_t dst, const void* src) {
    asm volatile("cp.async.cg.shared.global [%0], [%1], 16;" :: "r"(dst), "l"(src) : "memory");
}
#define CP_COMMIT() asm volatile("cp.async.commit_group;" ::: "memory")
#define CP_WAIT(n)  asm volatile("cp.async.wait_group %0;" :: "n"(n) : "memory")

__device__ __forceinline__ void ldm4(uint32_t* r, uint32_t addr) {
    asm volatile("ldmatrix.sync.aligned.m8n8.x4.shared.b16 {%0,%1,%2,%3}, [%4];"
        : "=r"(r[0]), "=r"(r[1]), "=r"(r[2]), "=r"(r[3]) : "r"(addr));
}
__device__ __forceinline__ void ldm4t(uint32_t* r, uint32_t addr) {
    asm volatile("ldmatrix.sync.aligned.m8n8.x4.trans.shared.b16 {%0,%1,%2,%3}, [%4];"
        : "=r"(r[0]), "=r"(r[1]), "=r"(r[2]), "=r"(r[3]) : "r"(addr));
}
__device__ __forceinline__ void mma16816(float* d, const uint32_t* a, const uint32_t* b) {
    asm volatile("mma.sync.aligned.m16n8k16.row.col.f32.bf16.bf16.f32 "
        "{%0,%1,%2,%3}, {%4,%5,%6,%7}, {%8,%9}, {%0,%1,%2,%3};"
        : "+f"(d[0]), "+f"(d[1]), "+f"(d[2]), "+f"(d[3])
        : "r"(a[0]), "r"(a[1]), "r"(a[2]), "r"(a[3]), "r"(b[0]), "r"(b[1]));
}

// ---------------------------------------------------------------------------
// LayerNorm + ReLU -> bf16 hi/lo (fused; no fp32 intermediate)
// ---------------------------------------------------------------------------
__global__ void ln_relu_split_kernel(const float* __restrict__ in,
                                     const float* __restrict__ gamma,
                                     const float* __restrict__ beta,
                                     __nv_bfloat16* __restrict__ hi,
                                     __nv_bfloat16* __restrict__ lo) {
    int row = blockIdx.x;
    int tid = threadIdx.x;
    const float* p = in + (size_t)row * DD + tid * 4;
    float4 xv = *(const float4*)p;

    float s  = xv.x + xv.y + xv.z + xv.w;
    float ss = xv.x*xv.x + xv.y*xv.y + xv.z*xv.z + xv.w*xv.w;
    #pragma unroll
    for (int off = 16; off > 0; off >>= 1) {
        s  += __shfl_xor_sync(0xffffffffu, s,  off);
        ss += __shfl_xor_sync(0xffffffffu, ss, off);
    }
    __shared__ float sbuf[8], ssbuf[8];
    __shared__ float smean, sinv;
    int lane = tid & 31, warp = tid >> 5;
    if (lane == 0) { sbuf[warp] = s; ssbuf[warp] = ss; }
    __syncthreads();
    if (tid == 0) {
        float ts = 0.f, tss = 0.f;
        #pragma unroll
        for (int i = 0; i < 8; i++) { ts += sbuf[i]; tss += ssbuf[i]; }
        float mean = ts * (1.0f / DD);
        float var  = tss * (1.0f / DD) - mean * mean;
        smean = mean;
        sinv  = rsqrtf(var + 1e-5f);
    }
    __syncthreads();
    float m = smean, inv = sinv;

    int c = tid * 4;
    float4 g4 = *(const float4*)(gamma + c);
    float4 b4 = *(const float4*)(beta  + c);
    float o0 = fmaxf(0.f, (xv.x - m) * inv * g4.x + b4.x);
    float o1 = fmaxf(0.f, (xv.y - m) * inv * g4.y + b4.y);
    float o2 = fmaxf(0.f, (xv.z - m) * inv * g4.z + b4.z);
    float o3 = fmaxf(0.f, (xv.w - m) * inv * g4.w + b4.w);

    __nv_bfloat162 h0 = __floats2bfloat162_rn(o0, o1);
    __nv_bfloat162 h1 = __floats2bfloat162_rn(o2, o3);
    __nv_bfloat162 l0 = __floats2bfloat162_rn(o0 - __bfloat162float(h0.x),
                                              o1 - __bfloat162float(h0.y));
    __nv_bfloat162 l1 = __floats2bfloat162_rn(o2 - __bfloat162float(h1.x),
                                              o3 - __bfloat162float(h1.y));
    size_t base = (size_t)row * DD + c;
    *(__nv_bfloat162*)(hi + base)     = h0;
    *(__nv_bfloat162*)(hi + base + 2) = h1;
    *(__nv_bfloat162*)(lo + base)     = l0;
    *(__nv_bfloat162*)(lo + base + 2) = l1;
}

// ---------------------------------------------------------------------------
// Transpose + split: W[K=1024, N=1024] fp32 -> Wt_hi/Wt_lo [N, K] bf16
// ---------------------------------------------------------------------------
__global__ void transpose_split_kernel(const float* __restrict__ W,
                                       __nv_bfloat16* __restrict__ hi,
                                       __nv_bfloat16* __restrict__ lo) {
    __shared__ float tile[32][33];
    int tx = threadIdx.x, ty = threadIdx.y;          // 32 x 8
    int n0 = blockIdx.x * 32, k0 = blockIdx.y * 32;
    #pragma unroll
    for (int i = 0; i < 4; i++) {
        int kr = ty + i * 8;
        tile[kr][tx] = W[(size_t)(k0 + kr) * DD + n0 + tx];
    }
    __syncthreads();
    #pragma unroll
    for (int i = 0; i < 4; i++) {
        int nr = ty + i * 8;
        float v = tile[tx][nr];
        __nv_bfloat16 h = __float2bfloat16_rn(v);
        __nv_bfloat16 l = __float2bfloat16_rn(v - __bfloat162float(h));
        hi[(size_t)(n0 + nr) * DD + k0 + tx] = h;
        lo[(size_t)(n0 + nr) * DD + k0 + tx] = l;
    }
}

// ---------------------------------------------------------------------------
// HMMA GEMM: C[4096,1024] = A @ Wt^T (+bias, +res).  3-term hi/lo Markidis.
// CTA tile 256x128, BK=64, double-buffered cp.async, 8 warps (4M x 2N),
// warp tile 64x64.  Grid (8, 16) = 128 CTAs = one full wave.
// smem: Ah[2]=64K  Al[2]=64K  Bh[2]=32K  Bl[2]=32K  -> 192K
// ---------------------------------------------------------------------------
#define GA_OFF(buf)  ((buf) * 32768)
#define GAL_OFF(buf) (65536 + (buf) * 32768)
#define GB_OFF(buf)  (131072 + (buf) * 16384)
#define GBL_OFF(buf) (163840 + (buf) * 16384)
#define GT_SMEM 196608

struct GPtrs { const char *ahi, *alo, *bhi, *blo; };

__device__ __forceinline__ void gt_load_chunk(uint32_t sb, int buf,
                                              const GPtrs& g, int chunk, int tid) {
    size_t kbyte = (size_t)chunk * 128;
    // A tiles: 256 rows x 128B (hi, lo)
    #pragma unroll
    for (int t = 0; t < 2; t++) {
        uint32_t base = sb + (t ? GAL_OFF(buf) : GA_OFF(buf));
        const char* src = t ? g.alo : g.ahi;
        #pragma unroll
        for (int it = 0; it < 8; it++) {
            int idx = tid + it * 256;               // 0..2047
            int r = idx >> 3;
            int c16 = idx & 7;
            uint32_t so = (uint32_t)(r * 128 + c16 * 16);
            uint32_t sw = so ^ ((so >> 3) & 0x70);
            cpasync16(base + sw, src + (size_t)r * 2048 + kbyte + c16 * 16);
        }
    }
    // B tiles: 128 rows x 128B (hi, lo)
    #pragma unroll
    for (int t = 0; t < 2; t++) {
        uint32_t base = sb + (t ? GBL_OFF(buf) : GB_OFF(buf));
        const char* src = t ? g.blo : g.bhi;
        #pragma unroll
        for (int it = 0; it < 4; it++) {
            int idx = tid + it * 256;               // 0..1023
            int r = idx >> 3;
            int c16 = idx & 7;
            uint32_t so = (uint32_t)(r * 128 + c16 * 16);
            uint32_t sw = so ^ ((so >> 3) & 0x70);
            cpasync16(base + sw, src + (size_t)r * 2048 + kbyte + c16 * 16);
        }
    }
}

__global__ void __launch_bounds__(256, 1)
gemm_hmma(const __nv_bfloat16* __restrict__ Ahi, const __nv_bfloat16* __restrict__ Alo,
          const __nv_bfloat16* __restrict__ Bhi, const __nv_bfloat16* __restrict__ Blo,
          const float* __restrict__ bias, const float* __restrict__ res,
          float* __restrict__ C,
          __nv_bfloat16* __restrict__ Chi, __nv_bfloat16* __restrict__ Clo) {
    extern __shared__ char smem[];
    uint32_t sb = smem_u32(smem);
    int tid = threadIdx.x;
    int lane = tid & 31;
    int wid = tid >> 5;
    int wm = wid & 3;                // 0..3 (M, 64 rows each)
    int wn = wid >> 2;               // 0..1 (N, 64 cols each)

    int n0 = blockIdx.x * 128;
    int m0 = blockIdx.y * 256;

    GPtrs g;
    g.ahi = (const char*)(Ahi + (size_t)m0 * DD);
    g.alo = (const char*)(Alo + (size_t)m0 * DD);
    g.bhi = (const char*)(Bhi + (size_t)n0 * DD);
    g.blo = (const char*)(Blo + (size_t)n0 * DD);

    float acc[4][8][4];
    #pragma unroll
    for (int i = 0; i < 4; i++)
        #pragma unroll
        for (int j = 0; j < 8; j++)
            #pragma unroll
            for (int r = 0; r < 4; r++) acc[i][j][r] = 0.f;

    uint32_t aRow = (uint32_t)(wm * 64 + (lane & 15));
    uint32_t xorb = (uint32_t)((lane & 7) * 16);
    uint32_t aHi  = (uint32_t)(((lane >> 4) & 1) * 16);
    uint32_t bRow = (uint32_t)(wn * 64 + ((lane >> 4) & 1) * 8 + (lane & 7));
    uint32_t bHi  = (uint32_t)(((lane >> 3) & 1) * 16);

    gt_load_chunk(sb, 0, g, 0, tid);
    CP_COMMIT();

    #pragma unroll 1
    for (int c = 0; c < 16; c++) {
        int buf = c & 1;
        if (c < 15) {
            gt_load_chunk(sb, buf ^ 1, g, c + 1, tid);
            CP_COMMIT();
            CP_WAIT(1);
        } else {
            CP_WAIT(0);
        }
        __syncthreads();

        uint32_t tAh = sb + GA_OFF(buf);
        uint32_t tAl = sb + GAL_OFF(buf);
        uint32_t tBh = sb + GB_OFF(buf);
        uint32_t tBl = sb + GBL_OFF(buf);

        #pragma unroll
        for (int ks = 0; ks < 4; ks++) {
            uint32_t ka = ((uint32_t)(ks * 32) + aHi) ^ xorb;
            uint32_t kb = ((uint32_t)(ks * 32) + bHi) ^ xorb;

            uint32_t Ah[4][4], Al[4][4];
            #pragma unroll
            for (int i = 0; i < 4; i++) {
                uint32_t ro = (aRow + 16 * i) * 128;
                ldm4(Ah[i], tAh + ro + ka);
                ldm4(Al[i], tAl + ro + ka);
            }
            #pragma unroll
            for (int jp = 0; jp < 4; jp++) {
                uint32_t ro = (bRow + 16 * jp) * 128;
                uint32_t Bh[4], Bl[4];
                ldm4(Bh, tBh + ro + kb);
                ldm4(Bl, tBl + ro + kb);
                #pragma unroll
                for (int i = 0; i < 4; i++) {
                    #pragma unroll
                    for (int jh = 0; jh < 2; jh++) {
                        float* d = acc[i][jp * 2 + jh];
                        mma16816(d, Ah[i], &Bh[jh * 2]);
                        mma16816(d, Ah[i], &Bl[jh * 2]);
                        mma16816(d, Al[i], &Bh[jh * 2]);
                    }
                }
            }
        }
        __syncthreads();
    }

    int rbase = m0 + wm * 64 + (lane >> 2);
    int cbase = n0 + wn * 64 + (lane & 3) * 2;
    #pragma unroll
    for (int j = 0; j < 8; j++) {
        int cc = cbase + 8 * j;
        float2 b2 = *(const float2*)(bias + cc);
        #pragma unroll
        for (int i = 0; i < 4; i++) {
            int r = rbase + 16 * i;
            float2 o0 = {acc[i][j][0] + b2.x, acc[i][j][1] + b2.y};
            float2 o1 = {acc[i][j][2] + b2.x, acc[i][j][3] + b2.y};
            size_t off0 = (size_t)r * DD + cc;
            size_t off1 = (size_t)(r + 8) * DD + cc;
            if (Chi) {
                __nv_bfloat162 h0 = __floats2bfloat162_rn(o0.x, o0.y);
                __nv_bfloat162 h1 = __floats2bfloat162_rn(o1.x, o1.y);
                __nv_bfloat162 l0 = __floats2bfloat162_rn(
                    o0.x - __bfloat162float(h0.x), o0.y - __bfloat162float(h0.y));
                __nv_bfloat162 l1 = __floats2bfloat162_rn(
                    o1.x - __bfloat162float(h1.x), o1.y - __bfloat162float(h1.y));
                *(__nv_bfloat162*)(Chi + off0) = h0;
                *(__nv_bfloat162*)(Chi + off1) = h1;
                *(__nv_bfloat162*)(Clo + off0) = l0;
                *(__nv_bfloat162*)(Clo + off1) = l1;
            } else {
                if (res) {
                    float2 r0 = *(const float2*)(res + off0);
                    float2 r1 = *(const float2*)(res + off1);
                    o0.x += r0.x; o0.y += r0.y;
                    o1.x += r1.x; o1.y += r1.y;
                }
                *(float2*)(C + off0) = o0;
                *(float2*)(C + off1) = o1;
            }
        }
    }
}

// ---------------------------------------------------------------------------
// Fused flash attention (bf16 HMMA, hi/lo 3-term). Output bf16 hi/lo.
// Grid: (TQ/128 = 8, BH = 64), 256 threads (8 warps, 16 q-rows each).
// ---------------------------------------------------------------------------
#define FA_KBUF(buf) (32768 + (buf) * 32768)
#define FA_SMEM      (98304 + 512)

__global__ void __launch_bounds__(256, 1)
flash_kernel(const __nv_bfloat16* __restrict__ Qhi, const __nv_bfloat16* __restrict__ Qlo,
             const __nv_bfloat16* __restrict__ Khi, const __nv_bfloat16* __restrict__ Klo,
             const __nv_bfloat16* __restrict__ Vhi, const __nv_bfloat16* __restrict__ Vlo,
             const int* __restrict__ mask,
             __nv_bfloat16* __restrict__ Ohi, __nv_bfloat16* __restrict__ Olo) {
    extern __shared__ char smem[];
    uint32_t sb = smem_u32(smem);
    int tid = threadIdx.x;
    int lane = tid & 31, wid = tid >> 5;
    int qtile = blockIdx.x;
    int bh = blockIdx.y;
    int b = bh >> 4, h = bh & 15;

    size_t qrow0 = (size_t)b * TQ + (size_t)qtile * 128;
    size_t krow0 = (size_t)b * TK;
    uint32_t hbyte = (uint32_t)h * 128;

    uint32_t sQh = sb, sQl = sb + 16384;
    float* mfbase = (float*)(smem + 98304);

    {
        const char* gh = (const char*)Qhi;
        const char* gl = (const char*)Qlo;
        #pragma unroll
        for (int it = 0; it < 4; it++) {
            int idx = tid + it * 256;
            int r = idx >> 3, c16 = (idx & 7) * 16;
            uint32_t so = (uint32_t)(r * 128 + c16);
            uint32_t sw = so ^ ((so >> 3) & 0x70);
            size_t go = (qrow0 + r) * 2048 + hbyte + c16;
            cpasync16(sQh + sw, gh + go);
            cpasync16(sQl + sw, gl + go);
        }
    }

    const char* gK[2] = {(const char*)Khi, (const char*)Klo};
    const char* gV[2] = {(const char*)Vhi, (const char*)Vlo};

    {
        uint32_t base = sb + FA_KBUF(0);
        #pragma unroll
        for (int t = 0; t < 4; t++) {
            const char* src = (t < 2) ? gK[t] : gV[t - 2];
            uint32_t tb = base + t * 8192;
            #pragma unroll
            for (int it = 0; it < 2; it++) {
                int idx = tid + it * 256;
                int r = idx >> 3, c16 = (idx & 7) * 16;
                uint32_t so = (uint32_t)(r * 128 + c16);
                uint32_t sw = so ^ ((so >> 3) & 0x70);
                cpasync16(tb + sw, src + (krow0 + r) * 2048 + hbyte + c16);
            }
        }
    }
    CP_COMMIT();
    if (tid < 64) mfbase[tid] = mask[(size_t)b * TK + tid] ? 1.f : 0.f;
    {
        uint32_t base = sb + FA_KBUF(1);
        #pragma unroll
        for (int t = 0; t < 4; t++) {
            const char* src = (t < 2) ? gK[t] : gV[t - 2];
            uint32_t tb = base + t * 8192;
            #pragma unroll
            for (int it = 0; it < 2; it++) {
                int idx = tid + it * 256;
                int r = idx >> 3, c16 = (idx & 7) * 16;
                uint32_t so = (uint32_t)(r * 128 + c16);
                uint32_t sw = so ^ ((so >> 3) & 0x70);
                cpasync16(tb + sw, src + (krow0 + 64 + r) * 2048 + hbyte + c16);
            }
        }
    }
    CP_COMMIT();
    if (tid < 64) mfbase[64 + tid] = mask[(size_t)b * TK + 64 + tid] ? 1.f : 0.f;

    uint32_t xorb = (uint32_t)((lane & 7) * 16);
    uint32_t aHi  = (uint32_t)(((lane >> 4) & 1) * 16);
    uint32_t kRowBase = 8 * ((lane >> 4) & 1) + (lane & 7);
    uint32_t kColHalf = 16 * ((lane >> 3) & 1);
    uint32_t vRowBase = 8 * ((lane >> 3) & 1) + (lane & 7);
    uint32_t vColHalf = 16 * ((lane >> 4) & 1);

    float O[8][4];
    #pragma unroll
    for (int f = 0; f < 8; f++)
        #pragma unroll
        for (int r = 0; r < 4; r++) O[f][r] = 0.f;
    float mrow0 = -INFINITY, mrow1 = -INFINITY;
    float lrow0 = 0.f, lrow1 = 0.f;
    uint32_t QhF[4][4], QlF[4][4];

    #pragma unroll 1
    for (int c = 0; c < 16; c++) {
        int buf = c & 1;
        if (c < 15) { CP_WAIT(1); } else { CP_WAIT(0); }
        __syncthreads();

        if (c == 0) {
            #pragma unroll
            for (int ks = 0; ks < 4; ks++) {
                uint32_t row = (uint32_t)(wid * 16 + (lane & 15));
                uint32_t col = ((uint32_t)(ks * 32) + aHi) ^ xorb;
                ldm4(QhF[ks], sQh + row * 128 + col);
                ldm4(QlF[ks], sQl + row * 128 + col);
            }
        }

        uint32_t sKh = sb + FA_KBUF(buf);
        uint32_t sKl = sKh + 8192;
        uint32_t sVh = sKh + 16384;
        uint32_t sVl = sKh + 24576;
        const float* mf = mfbase + buf * 64;

        float S[8][4];
        #pragma unroll
        for (int n = 0; n < 8; n++)
            #pragma unroll
            for (int r = 0; r < 4; r++) S[n][r] = 0.f;

        #pragma unroll
        for (int ks = 0; ks < 4; ks++) {
            uint32_t col = ((uint32_t)(ks * 32) + kColHalf) ^ xorb;
            #pragma unroll
            for (int np = 0; np < 4; np++) {
                uint32_t KhF[4], KlF[4];
                uint32_t ro = (np * 16 + kRowBase) * 128;
                ldm4(KhF, sKh + ro + col);
                ldm4(KlF, sKl + ro + col);
                mma16816(S[np*2],   QhF[ks], KhF);
                mma16816(S[np*2],   QhF[ks], KlF);
                mma16816(S[np*2],   QlF[ks], KhF);
                mma16816(S[np*2+1], QhF[ks], KhF + 2);
                mma16816(S[np*2+1], QhF[ks], KlF + 2);
                mma16816(S[np*2+1], QlF[ks], KhF + 2);
            }
        }

        #pragma unroll
        for (int n = 0; n < 8; n++) {
            int j = 8 * n + (lane & 3) * 2;
            float mk0 = mf[j], mk1 = mf[j + 1];
            S[n][0] = (mk0 != 0.f) ? S[n][0] * 0.125f : -1e30f;
            S[n][1] = (mk1 != 0.f) ? S[n][1] * 0.125f : -1e30f;
            S[n][2] = (mk0 != 0.f) ? S[n][2] * 0.125f : -1e30f;
            S[n][3] = (mk1 != 0.f) ? S[n][3] * 0.125f : -1e30f;
        }

        float cm0 = -INFINITY, cm1 = -INFINITY;
        #pragma unroll
        for (int n = 0; n < 8; n++) {
            cm0 = fmaxf(cm0, fmaxf(S[n][0], S[n][1]));
            cm1 = fmaxf(cm1, fmaxf(S[n][2], S[n][3]));
        }
        cm0 = fmaxf(cm0, __shfl_xor_sync(0xffffffffu, cm0, 1));
        cm0 = fmaxf(cm0, __shfl_xor_sync(0xffffffffu, cm0, 2));
        cm1 = fmaxf(cm1, __shfl_xor_sync(0xffffffffu, cm1, 1));
        cm1 = fmaxf(cm1, __shfl_xor_sync(0xffffffffu, cm1, 2));

        float mn0 = fmaxf(mrow0, cm0);
        float mn1 = fmaxf(mrow1, cm1);
        float al0 = __expf(mrow0 - mn0);
        float al1 = __expf(mrow1 - mn1);
        mrow0 = mn0; mrow1 = mn1;

        uint32_t Phi[4][4], Plo[4][4];
        float sum0 = 0.f, sum1 = 0.f;
        #pragma unroll
        for (int n = 0; n < 8; n++) {
            float p0 = __expf(S[n][0] - mn0);
            float p1 = __expf(S[n][1] - mn0);
            float p2 = __expf(S[n][2] - mn1);
            float p3 = __expf(S[n][3] - mn1);
            sum0 += p0 + p1;
            sum1 += p2 + p3;
            __nv_bfloat162 h01 = __floats2bfloat162_rn(p0, p1);
            __nv_bfloat162 h23 = __floats2bfloat162_rn(p2, p3);
            __nv_bfloat162 l01 = __floats2bfloat162_rn(
                p0 - __bfloat162float(h01.x), p1 - __bfloat162float(h01.y));
            __nv_bfloat162 l23 = __floats2bfloat162_rn(
                p2 - __bfloat162float(h23.x), p3 - __bfloat162float(h23.y));
            int kk = n >> 1, base = (n & 1) * 2;
            Phi[kk][base]     = *(uint32_t*)&h01;
            Phi[kk][base + 1] = *(uint32_t*)&h23;
            Plo[kk][base]     = *(uint32_t*)&l01;
            Plo[kk][base + 1] = *(uint32_t*)&l23;
        }
        sum0 += __shfl_xor_sync(0xffffffffu, sum0, 1);
        sum0 += __shfl_xor_sync(0xffffffffu, sum0, 2);
        sum1 += __shfl_xor_sync(0xffffffffu, sum1, 1);
        sum1 += __shfl_xor_sync(0xffffffffu, sum1, 2);
        lrow0 = lrow0 * al0 + sum0;
        lrow1 = lrow1 * al1 + sum1;
        #pragma unroll
        for (int f = 0; f < 8; f++) {
            O[f][0] *= al0; O[f][1] *= al0;
            O[f][2] *= al1; O[f][3] *= al1;
        }

        #pragma unroll
        for (int ks = 0; ks < 4; ks++) {
            uint32_t ro = (ks * 16 + vRowBase) * 128;
            #pragma unroll
            for (int dp = 0; dp < 4; dp++) {
                uint32_t col = ((uint32_t)(dp * 32) + vColHalf) ^ xorb;
                uint32_t VhF[4], VlF[4];
                ldm4t(VhF, sVh + ro + col);
                ldm4t(VlF, sVl + ro + col);
                mma16816(O[dp*2],   Phi[ks], VhF);
                mma16816(O[dp*2],   Phi[ks], VlF);
                mma16816(O[dp*2],   Plo[ks], VhF);
                mma16816(O[dp*2+1], Phi[ks], VhF + 2);
                mma16816(O[dp*2+1], Phi[ks], VlF + 2);
                mma16816(O[dp*2+1], Plo[ks], VhF + 2);
            }
        }

        __syncthreads();
        if (c < 14) {
            int T0 = (c + 2) * 64;
            uint32_t base = sb + FA_KBUF(buf);
            #pragma unroll
            for (int t = 0; t < 4; t++) {
                const char* src = (t < 2) ? gK[t] : gV[t - 2];
                uint32_t tb = base + t * 8192;
                #pragma unroll
                for (int it = 0; it < 2; it++) {
                    int idx = tid + it * 256;
                    int r = idx >> 3, c16 = (idx & 7) * 16;
                    uint32_t so = (uint32_t)(r * 128 + c16);
                    uint32_t sw = so ^ ((so >> 3) & 0x70);
                    cpasync16(tb + sw, src + (krow0 + T0 + r) * 2048 + hbyte + c16);
                }
            }
            CP_COMMIT();
            if (tid < 64)
                mfbase[buf * 64 + tid] = mask[(size_t)b * TK + T0 + tid] ? 1.f : 0.f;
        }
    }

    float rinv0 = 1.f / lrow0;
    float rinv1 = 1.f / lrow1;
    int grow = (int)qrow0 + wid * 16 + (lane >> 2);
    int col0 = h * 64 + (lane & 3) * 2;
    #pragma unroll
    for (int f = 0; f < 8; f++) {
        int cc = col0 + 8 * f;
        float v0 = O[f][0] * rinv0, v1 = O[f][1] * rinv0;
        float v2 = O[f][2] * rinv1, v3 = O[f][3] * rinv1;
        __nv_bfloat162 h0 = __floats2bfloat162_rn(v0, v1);
        __nv_bfloat162 h1 = __floats2bfloat162_rn(v2, v3);
        __nv_bfloat162 l0 = __floats2bfloat162_rn(v0 - __bfloat162float(h0.x),
                                                  v1 - __bfloat162float(h0.y));
        __nv_bfloat162 l1 = __floats2bfloat162_rn(v2 - __bfloat162float(h1.x),
                                                  v3 - __bfloat162float(h1.y));
        size_t off0 = (size_t)grow * DD + cc;
        size_t off1 = (size_t)(grow + 8) * DD + cc;
        *(__nv_bfloat162*)(Ohi + off0) = h0;
        *(__nv_bfloat162*)(Ohi + off1) = h1;
        *(__nv_bfloat162*)(Olo + off0) = l0;
        *(__nv_bfloat162*)(Olo + off1) = l1;
    }
}

// ---------------------------------------------------------------------------
// Launch
// ---------------------------------------------------------------------------
extern "C" void kernel_launch(void* const* d_in, const int* in_sizes, int n_in,
                              void* d_out, int out_size) {
    const float* x      = (const float*)d_in[0];
    const float* y      = (const float*)d_in[1];
    const int*   mask   = (const int*)d_in[2];
    const float* ln1_g  = (const float*)d_in[3];
    const float* ln1_b  = (const float*)d_in[4];
    const float* ln2_g  = (const float*)d_in[5];
    const float* ln2_b  = (const float*)d_in[6];
    const float* q_w    = (const float*)d_in[7];
    const float* q_b    = (const float*)d_in[8];
    const float* k_w    = (const float*)d_in[9];
    const float* k_b    = (const float*)d_in[10];
    const float* v_w    = (const float*)d_in[11];
    const float* v_b    = (const float*)d_in[12];
    const float* o_w    = (const float*)d_in[13];
    const float* o_b    = (const float*)d_in[14];
    const float* mln1_g = (const float*)d_in[15];
    const float* mln1_b = (const float*)d_in[16];
    const float* l1_w   = (const float*)d_in[17];
    const float* l1_b   = (const float*)d_in[18];
    const float* mln2_g = (const float*)d_in[19];
    const float* mln2_b = (const float*)d_in[20];
    const float* l2_w   = (const float*)d_in[21];
    const float* l2_b   = (const float*)d_in[22];
    float* out = (float*)d_out;

    float *x2, *hbuf;
    __nv_bfloat16 *xhi, *xlo, *yhi, *ylo, *phi, *plo, *bhi, *blo;
    __nv_bfloat16 *qhi, *qlo, *khi, *klo, *vhi, *vlo;
    cudaGetSymbolAddress((void**)&x2,   g_x2);
    cudaGetSymbolAddress((void**)&hbuf, g_h);
    cudaGetSymbolAddress((void**)&xhi,  g_xhi);
    cudaGetSymbolAddress((void**)&xlo,  g_xlo);
    cudaGetSymbolAddress((void**)&yhi,  g_yhi);
    cudaGetSymbolAddress((void**)&ylo,  g_ylo);
    cudaGetSymbolAddress((void**)&phi,  g_phi);
    cudaGetSymbolAddress((void**)&plo,  g_plo);
    cudaGetSymbolAddress((void**)&bhi,  g_bhi);
    cudaGetSymbolAddress((void**)&blo,  g_blo);
    cudaGetSymbolAddress((void**)&qhi,  g_qhi);
    cudaGetSymbolAddress((void**)&qlo,  g_qlo);
    cudaGetSymbolAddress((void**)&khi,  g_khi);
    cudaGetSymbolAddress((void**)&klo,  g_klo);
    cudaGetSymbolAddress((void**)&vhi,  g_vhi);
    cudaGetSymbolAddress((void**)&vlo,  g_vlo);

    cudaFuncSetAttribute(gemm_hmma, cudaFuncAttributeMaxDynamicSharedMemorySize, GT_SMEM);
    cudaFuncSetAttribute(flash_kernel, cudaFuncAttributeMaxDynamicSharedMemorySize, FA_SMEM);

    dim3 gemmGrid(8, 16);                       // N/128, M/256 = 128 CTAs
    dim3 tGrid(32, 32);
    dim3 tBlock(32, 8);

    // 1) pre-norms -> bf16 hi/lo directly
    ln_relu_split_kernel<<<MROWS, 256>>>(x, ln1_g, ln1_b, xhi, xlo);
    ln_relu_split_kernel<<<BB * TK, 256>>>(y, ln2_g, ln2_b, yhi, ylo);

    // 2) q/k/v projections -> bf16 hi/lo directly
    transpose_split_kernel<<<tGrid, tBlock>>>(q_w, bhi, blo);
    gemm_hmma<<<gemmGrid, 256, GT_SMEM>>>(xhi, xlo, bhi, blo, q_b, nullptr,
                                          nullptr, qhi, qlo);
    transpose_split_kernel<<<tGrid, tBlock>>>(k_w, bhi, blo);
    gemm_hmma<<<gemmGrid, 256, GT_SMEM>>>(yhi, ylo, bhi, blo, k_b, nullptr,
                                          nullptr, khi, klo);
    transpose_split_kernel<<<tGrid, tBlock>>>(v_w, bhi, blo);
    gemm_hmma<<<gemmGrid, 256, GT_SMEM>>>(yhi, ylo, bhi, blo, v_b, nullptr,
                                          nullptr, vhi, vlo);

    // 3) fused flash attention -> bf16 hi/lo
    flash_kernel<<<dim3(8, BH), 256, FA_SMEM>>>(qhi, qlo, khi, klo, vhi, vlo,
                                                mask, phi, plo);

    // 4) output proj + residual (fp32 out)
    transpose_split_kernel<<<tGrid, tBlock>>>(o_w, bhi, blo);
    gemm_hmma<<<gemmGrid, 256, GT_SMEM>>>(phi, plo, bhi, blo, o_b, x,
                                          x2, nullptr, nullptr);

    // 5) MLP
    ln_relu_split_kernel<<<MROWS, 256>>>(x2, mln1_g, mln1_b, xhi, xlo);
    transpose_split_kernel<<<tGrid, tBlock>>>(l1_w, bhi, blo);
    gemm_hmma<<<gemmGrid, 256, GT_SMEM>>>(xhi, xlo, bhi, blo, l1_b, nullptr,
                                          hbuf, nullptr, nullptr);

    ln_relu_split_kernel<<<MROWS, 256>>>(hbuf, mln2_g, mln2_b, yhi, ylo);
    transpose_split_kernel<<<tGrid, tBlock>>>(l2_w, bhi, blo);
    gemm_hmma<<<gemmGrid, 256, GT_SMEM>>>(yhi, ylo, bhi, blo, l2_b, nullptr,
                                          out, nullptr, nullptr);
}